// round 15
// baseline (speedup 1.0000x reference)
#include <cuda_runtime.h>
#include <math.h>
#include <stdint.h>

#define BATCH 4
#define HH 256
#define WW 256
#define HW 65536
#define C1 64
#define C2 128
#define NPAT 30
#define NANOM 32
#define QCIN 190

// d_out element offsets (outputs concatenated in reference return order)
#define FEAT_OFF 0UL
#define RL_OFF   33554432UL
#define AL_OFF   34340864UL
#define AM_OFF   34603008UL
#define ANM_OFF  42467328UL
#define QS_OFF   50855936UL
#define RP_OFF   51118080UL
#define AP_OFF   51904512UL

// ---------------------------------------------------------------------------
// device globals (no allocations allowed)
// ---------------------------------------------------------------------------
__device__ float  g_h1n[BATCH * HW * C1];     // conv1 out NHWC raw; after apply1: tf32(relu(bn1)) ch-permuted
__device__ float  g_feat[BATCH * HW * C2];    // conv2 out NHWC raw; after bn2t: tf32(relu(bn2)) ch-permuted
__device__ float  g_stats1[2 * C1];           // [a | s] affine for bn1
__device__ float  g_stats2[2 * C2];           // [a | s] affine for bn2
__device__ float  g_w2p[9 * 2 * 128 * 32];    // conv2 weights packed, k-permuted, tf32
__device__ float  g_mwp[9 * 4 * 64 * 32];     // matcher weights packed, k-permuted, tf32
__device__ float  g_psumf[128 * 2048];        // stats partials (fp32)
__device__ float  g_psqf[128 * 2048];

__device__ __forceinline__ float sigmoidf_(float v) {
    return 1.f / (1.f + __expf(-v));
}
__device__ __forceinline__ float to_tf32(float v) {
    uint32_t r;
    asm("cvt.rna.tf32.f32 %0, %1;" : "=r"(r) : "f"(v));
    return __uint_as_float(r);
}
__device__ __forceinline__ void mma_tf32(float* c,
                                         uint32_t a0, uint32_t a1, uint32_t a2, uint32_t a3,
                                         uint32_t b0, uint32_t b1) {
    asm volatile(
        "mma.sync.aligned.m16n8k8.row.col.f32.tf32.tf32.f32 "
        "{%0,%1,%2,%3}, {%4,%5,%6,%7}, {%8,%9}, {%0,%1,%2,%3};"
        : "+f"(c[0]), "+f"(c[1]), "+f"(c[2]), "+f"(c[3])
        : "r"(a0), "r"(a1), "r"(a2), "r"(a3), "r"(b0), "r"(b1));
}
// smem col c holds original k = invp(c); perm(k) = (k&3)*8 + (k>>2)
__device__ __forceinline__ int invp(int c) { return (c & 7) * 4 + (c >> 3); }

// ---------------------------------------------------------------------------
// conv1: 3 -> 64, 3x3 pad 1, bias. FFMA, NHWC out (natural channel order).
// z >= 16 planes do k-permuted weight packing instead.
// grid (8, 16, 21), block 256
// ---------------------------------------------------------------------------
__global__ void conv1_kernel(const float* __restrict__ x,
                             const float* __restrict__ w,
                             const float* __restrict__ bias,
                             const float* __restrict__ w2,
                             const float* __restrict__ core,
                             const float* __restrict__ clad,
                             const float* __restrict__ ferr,
                             const float* __restrict__ anom) {
    if (blockIdx.z >= 16) {
        int blk = ((blockIdx.z - 16) * 16 + blockIdx.y) * 8 + blockIdx.x;
        int i = blk * 256 + threadIdx.x;
        if (i < 9 * 2 * 128 * 32) {
            int k = i & 31, oc = (i >> 5) & 127, cc = (i >> 12) & 1, s = i >> 13;
            int ci = cc * 32 + invp(k);
            g_w2p[i] = to_tf32(w2[oc * 576 + ci * 9 + s]);
        } else if (i < 9 * 2 * 128 * 32 + 9 * 4 * 64 * 32) {
            int m = i - 9 * 2 * 128 * 32;
            int k = m & 31, oc = (m >> 5) & 63, cc = (m >> 11) & 3, s = m >> 13;
            int ci = cc * 32 + invp(k);
            float v = 0.f;
            if (oc < 10)      v = core[oc * 1152 + ci * 9 + s];
            else if (oc < 20) v = clad[(oc - 10) * 1152 + ci * 9 + s];
            else if (oc < 30) v = ferr[(oc - 20) * 1152 + ci * 9 + s];
            else if (oc < 62) v = anom[(oc - 30) * 1152 + ci * 9 + s];
            g_mwp[m] = to_tf32(v);
        }
        return;
    }

    __shared__ float s_in[3][18][34];
    __shared__ float s_w[27 * 16];
    __shared__ float s_ps[8][16];
    __shared__ float s_pq[8][16];
    int tid = threadIdx.x;
    int bx = blockIdx.x, by = blockIdx.y;
    int b = blockIdx.z >> 2, g = blockIdx.z & 3;
    int warp = tid >> 5, lane = tid & 31;

    for (int i = tid; i < 3 * 18 * 34; i += 256) {
        int ci = i / 612;
        int r = (i % 612) / 34;
        int c = i % 34;
        int y = by * 16 - 1 + r, xx = bx * 32 - 1 + c;
        float v = 0.f;
        if (y >= 0 && y < HH && xx >= 0 && xx < WW)
            v = x[((size_t)(b * 3 + ci)) * HW + (size_t)y * WW + xx];
        s_in[ci][r][c] = v;
    }
    for (int i = tid; i < 27 * 16; i += 256) {
        int o = i & 15, rest = i >> 4;
        s_w[i] = w[(g * 16 + o) * 27 + rest];
    }
    __syncthreads();

    int tx = tid & 15, ty = tid >> 4;
    float acc0[16], acc1[16];
#pragma unroll
    for (int o = 0; o < 16; ++o) {
        float bb = bias[g * 16 + o];
        acc0[o] = bb; acc1[o] = bb;
    }
#pragma unroll
    for (int ci = 0; ci < 3; ++ci)
#pragma unroll
        for (int k = 0; k < 9; ++k) {
            int ky = k / 3, kx = k % 3;
            float v0 = s_in[ci][ty + ky][tx + kx];
            float v1 = s_in[ci][ty + ky][tx + 16 + kx];
            const float* wp = &s_w[(ci * 9 + k) * 16];
#pragma unroll
            for (int o = 0; o < 16; ++o) {
                float ww = wp[o];
                acc0[o] = fmaf(v0, ww, acc0[o]);
                acc1[o] = fmaf(v1, ww, acc1[o]);
            }
        }
    int gy = by * 16 + ty, gx = bx * 32 + tx;
    size_t p0 = ((size_t)((b * HH + gy) * WW + gx)) * C1 + g * 16;
    size_t p1 = ((size_t)((b * HH + gy) * WW + gx + 16)) * C1 + g * 16;
#pragma unroll
    for (int o = 0; o < 16; ++o) {
        g_h1n[p0 + o] = acc0[o];
        g_h1n[p1 + o] = acc1[o];
    }

#pragma unroll
    for (int o = 0; o < 16; ++o) {
        float s = acc0[o] + acc1[o];
        float q = fmaf(acc0[o], acc0[o], acc1[o] * acc1[o]);
#pragma unroll
        for (int d = 16; d > 0; d >>= 1) {
            s += __shfl_xor_sync(0xffffffffu, s, d);
            q += __shfl_xor_sync(0xffffffffu, q, d);
        }
        if (lane == 0) { s_ps[warp][o] = s; s_pq[warp][o] = q; }
    }
    __syncthreads();
    if (tid < 16) {
        float s = 0.f, q = 0.f;
#pragma unroll
        for (int wp2 = 0; wp2 < 8; ++wp2) { s += s_ps[wp2][tid]; q += s_pq[wp2][tid]; }
        int ch = g * 16 + tid;
        int blk = bx + 8 * (by + 16 * b);
        g_psumf[ch * 512 + blk] = s;
        g_psqf[ch * 512 + blk] = q;
    }
}

// ---------------------------------------------------------------------------
// stats phase 2: reduce NP fp32 partials per channel in double -> affine.
// ---------------------------------------------------------------------------
template<int C, int NP>
__global__ void stats_p2v(const float* __restrict__ gamma,
                          const float* __restrict__ beta,
                          float* __restrict__ statsOut) {
    __shared__ double ss[256], sq[256];
    int c = blockIdx.x, tid = threadIdx.x;
    double s = 0.0, q = 0.0;
#pragma unroll
    for (int k = 0; k < NP / 256; ++k) {
        s += (double)g_psumf[c * NP + tid + k * 256];
        q += (double)g_psqf[c * NP + tid + k * 256];
    }
    ss[tid] = s; sq[tid] = q;
    __syncthreads();
    for (int st = 128; st > 0; st >>= 1) {
        if (tid < st) { ss[tid] += ss[tid + st]; sq[tid] += sq[tid + st]; }
        __syncthreads();
    }
    if (tid == 0) {
        double n = (double)BATCH * (double)HW;
        double mean = ss[0] / n;
        double var = sq[0] / n - mean * mean;
        double a = (double)gamma[c] / sqrt(var + 1e-5);
        statsOut[c] = (float)a;
        statsOut[C + c] = (float)((double)beta[c] - mean * a);
    }
}

// ---------------------------------------------------------------------------
// apply1: g_h1n <- tf32(relu(a*x+s)), channel-PERMUTED within each 32-block,
// in place via smem stage (block owns 16 px x 64 ch). grid 16384, block 256.
// ---------------------------------------------------------------------------
__global__ void apply1_kernel() {
    __shared__ float st[1024];
    int tid = threadIdx.x;
    size_t base = (size_t)blockIdx.x * 1024 + tid * 4;
    int ch0 = (tid * 4) & 63;
    float4 v = *(const float4*)&g_h1n[base];
    v.x = to_tf32(fmaxf(fmaf(g_stats1[ch0 + 0], v.x, g_stats1[C1 + ch0 + 0]), 0.f));
    v.y = to_tf32(fmaxf(fmaf(g_stats1[ch0 + 1], v.y, g_stats1[C1 + ch0 + 1]), 0.f));
    v.z = to_tf32(fmaxf(fmaf(g_stats1[ch0 + 2], v.z, g_stats1[C1 + ch0 + 2]), 0.f));
    v.w = to_tf32(fmaxf(fmaf(g_stats1[ch0 + 3], v.w, g_stats1[C1 + ch0 + 3]), 0.f));
    *(float4*)&st[tid * 4] = v;
    __syncthreads();
    int rowbase = tid * 4 - ch0;
    int blk32 = ch0 & 32;
    int t0 = ch0 & 31;
    float4 o;
    o.x = st[rowbase + blk32 + invp(t0 + 0)];
    o.y = st[rowbase + blk32 + invp(t0 + 1)];
    o.z = st[rowbase + blk32 + invp(t0 + 2)];
    o.w = st[rowbase + blk32 + invp(t0 + 3)];
    *(float4*)&g_h1n[base] = o;
}

// ---------------------------------------------------------------------------
// conv2: shift-reuse tf32 gemm (R14-proven). One B-tile (130 px x 32 ch,
// x-halo) per (ky,cc) serves all 3 kx shifts via shifted smem rows; A read
// directly via LDG from L2-resident packed weights. 6 chunks, 12 barriers.
// Epilogue: +bias -> NHWC g_feat + fused bn2-stats partials.
// grid (2, 256, BATCH), block 256 (warps 4M x 2N, tile 32x64).
// ---------------------------------------------------------------------------
__global__ __launch_bounds__(256, 2)
void conv2_kernel(const float* __restrict__ src,     // g_h1n, tf32 permuted NHWC
                  const float* __restrict__ wpack,   // g_w2p
                  const float* __restrict__ bias,
                  float* __restrict__ out) {         // g_feat NHWC
    constexpr int ROWW = 36;
    constexpr int BROWS = 136;             // rows 0..129 used (r = n + kx, px = x0-1+r)
    constexpr int BSZ = BROWS * ROWW;

    extern __shared__ float dsm[];
    uint32_t sbase = (uint32_t)__cvta_generic_to_shared(dsm);

    int tid = threadIdx.x;
    int warp = tid >> 5, lane = tid & 31;
    int warpM = warp & 3, warpN = warp >> 2;    // 4 x 2
    int lr = lane >> 2, lc = lane & 3;
    int jj = tid & 7;
    int pr = tid >> 3;                          // 0..31
    int x0 = blockIdx.x * 128;
    int y = blockIdx.y, b = blockIdx.z;

    auto issueB = [&](int j, int sel) {
        int ky = j >> 1, cc = j & 1;
        int yy = y + ky - 1;
        bool yok = (unsigned)yy < 256u;
        const char* srow = (const char*)(src
            + ((size_t)((b * 256 + (yok ? yy : 0)) * 256)) * 64 + cc * 32 + jj * 4);
        uint32_t dst0 = sbase + (uint32_t)(sel * (BSZ * 4) + pr * (ROWW * 4) + jj * 16);
#pragma unroll
        for (int t = 0; t < 5; ++t) {
            int r = pr + t * 32;
            if (r < 130) {
                int p = x0 - 1 + r;
                bool ok = yok && ((unsigned)p < 256u);
                const char* g = ok ? (srow + (size_t)p * 256) : (const char*)src;
                int sz = ok ? 16 : 0;
                uint32_t d = dst0 + (uint32_t)(t * (32 * ROWW * 4));
                asm volatile("cp.async.cg.shared.global [%0], [%1], 16, %2;"
                             :: "r"(d), "l"(g), "r"(sz));
            }
        }
        asm volatile("cp.async.commit_group;" ::: "memory");
    };

    float c[2][8][4];
#pragma unroll
    for (int fm = 0; fm < 2; ++fm)
#pragma unroll
        for (int fn = 0; fn < 8; ++fn)
#pragma unroll
            for (int t = 0; t < 4; ++t) c[fm][fn][t] = 0.f;

    issueB(0, 0);
    issueB(1, 1);

    for (int j = 0; j < 6; ++j) {
        int sel = j & 1;
        if (j < 5) asm volatile("cp.async.wait_group 1;" ::: "memory");
        else       asm volatile("cp.async.wait_group 0;" ::: "memory");
        __syncthreads();

        const float* Bs = dsm + sel * BSZ;
        int ky = j >> 1, cc = j & 1;
#pragma unroll
        for (int kx = 0; kx < 3; ++kx) {
            const float* Ab = wpack + (size_t)(((ky * 3 + kx) * 2 + cc) * 128) * 32;
#pragma unroll
            for (int ksp = 0; ksp < 2; ++ksp) {
                int colA = lc * 8 + ksp * 4;
                float4 a00 = *(const float4*)&Ab[(warpM * 32 + lr)      * 32 + colA];
                float4 a01 = *(const float4*)&Ab[(warpM * 32 + lr + 8)  * 32 + colA];
                float4 a10 = *(const float4*)&Ab[(warpM * 32 + lr + 16) * 32 + colA];
                float4 a11 = *(const float4*)&Ab[(warpM * 32 + lr + 24) * 32 + colA];
#pragma unroll
                for (int fn = 0; fn < 8; ++fn) {
                    int r = warpN * 64 + fn * 8 + lr + kx;
                    float4 bb = *(const float4*)&Bs[r * ROWW + colA];
                    uint32_t b0 = __float_as_uint(bb.x), b1 = __float_as_uint(bb.y);
                    uint32_t b2 = __float_as_uint(bb.z), b3 = __float_as_uint(bb.w);
                    mma_tf32(c[0][fn], __float_as_uint(a00.x), __float_as_uint(a01.x),
                                       __float_as_uint(a00.y), __float_as_uint(a01.y), b0, b1);
                    mma_tf32(c[1][fn], __float_as_uint(a10.x), __float_as_uint(a11.x),
                                       __float_as_uint(a10.y), __float_as_uint(a11.y), b0, b1);
                    mma_tf32(c[0][fn], __float_as_uint(a00.z), __float_as_uint(a01.z),
                                       __float_as_uint(a00.w), __float_as_uint(a01.w), b2, b3);
                    mma_tf32(c[1][fn], __float_as_uint(a10.z), __float_as_uint(a11.z),
                                       __float_as_uint(a10.w), __float_as_uint(a11.w), b2, b3);
                }
            }
        }
        __syncthreads();                       // all warps done reading buf sel
        if (j + 2 < 6) issueB(j + 2, sel);
    }

    // ---- epilogue: +bias -> NHWC out + fused bn2-stats partials ----
    {
        __shared__ float s_ps[2][128];
        __shared__ float s_pq[2][128];
        float rs[4], rq[4];
#pragma unroll
        for (int t = 0; t < 4; ++t) { rs[t] = 0.f; rq[t] = 0.f; }
#pragma unroll
        for (int fm = 0; fm < 2; ++fm) {
            int m0 = warpM * 32 + fm * 16 + lr;
            float bv0 = bias[m0], bv1 = bias[m0 + 8];
#pragma unroll
            for (int fn = 0; fn < 8; ++fn) {
                int px = x0 + warpN * 64 + fn * 8 + lc * 2;
                float* p = out + ((size_t)((b * 256 + y) * 256 + px)) * 128;
                float v0 = c[fm][fn][0] + bv0;
                float v1 = c[fm][fn][1] + bv0;
                float v2 = c[fm][fn][2] + bv1;
                float v3 = c[fm][fn][3] + bv1;
                p[m0]           = v0;
                p[128 + m0]     = v1;
                p[m0 + 8]       = v2;
                p[128 + m0 + 8] = v3;
                rs[fm * 2]     += v0 + v1;
                rq[fm * 2]      = fmaf(v0, v0, fmaf(v1, v1, rq[fm * 2]));
                rs[fm * 2 + 1] += v2 + v3;
                rq[fm * 2 + 1]  = fmaf(v2, v2, fmaf(v3, v3, rq[fm * 2 + 1]));
            }
        }
#pragma unroll
        for (int t = 0; t < 4; ++t) {
            rs[t] += __shfl_xor_sync(0xffffffffu, rs[t], 1);
            rs[t] += __shfl_xor_sync(0xffffffffu, rs[t], 2);
            rq[t] += __shfl_xor_sync(0xffffffffu, rq[t], 1);
            rq[t] += __shfl_xor_sync(0xffffffffu, rq[t], 2);
        }
        if (lc == 0) {
#pragma unroll
            for (int t = 0; t < 4; ++t) {
                int row = warpM * 32 + (t >> 1) * 16 + (t & 1) * 8 + lr;
                s_ps[warpN][row] = rs[t];
                s_pq[warpN][row] = rq[t];
            }
        }
        __syncthreads();
        if (tid < 128) {
            float s = s_ps[0][tid] + s_ps[1][tid];
            float q = s_pq[0][tid] + s_pq[1][tid];
            int cta = blockIdx.x + 2 * (blockIdx.y + 256 * blockIdx.z);
            g_psumf[tid * 2048 + cta] = s;
            g_psqf[tid * 2048 + cta] = q;
        }
    }
}

// ---------------------------------------------------------------------------
// matcher: shift-reuse tf32 gemm, conv2-mirrored NTILE=128 geometry.
// 2048 CTAs (6.9 waves vs 3.5), 39KB smem (frees ~150KB L1 for A-weight
// caching), 32 accum regs. Per-output accumulation order identical to R14.
// grid (2, 256, BATCH), block 256 (warps 2M x 4N, tile 32x32).
// ---------------------------------------------------------------------------
__global__ __launch_bounds__(256, 2)
void matcher_kernel(const float* __restrict__ src,     // g_feat, tf32 permuted NHWC
                    const float* __restrict__ wpack,   // g_mwp
                    float* __restrict__ out) {
    constexpr int ROWW = 36;
    constexpr int BROWS = 136;             // rows 0..129 used (r = n + kx, px = x0-1+r)
    constexpr int BSZ = BROWS * ROWW;

    extern __shared__ float dsm[];
    uint32_t sbase = (uint32_t)__cvta_generic_to_shared(dsm);

    int tid = threadIdx.x;
    int warp = tid >> 5, lane = tid & 31;
    int warpM = warp & 1, warpN = warp >> 1;    // 2 x 4
    int lr = lane >> 2, lc = lane & 3;
    int jj = tid & 7;
    int pr = tid >> 3;                          // 0..31
    int x0 = blockIdx.x * 128;
    int y = blockIdx.y, b = blockIdx.z;

    auto issueB = [&](int j, int sel) {
        int ky = j >> 2, cc = j & 3;
        int yy = y + ky - 1;
        bool yok = (unsigned)yy < 256u;
        const char* srow = (const char*)(src
            + ((size_t)((b * 256 + (yok ? yy : 0)) * 256)) * 128 + cc * 32 + jj * 4);
        uint32_t dst0 = sbase + (uint32_t)(sel * (BSZ * 4) + pr * (ROWW * 4) + jj * 16);
#pragma unroll
        for (int t = 0; t < 5; ++t) {
            int r = pr + t * 32;
            if (r < 130) {
                int p = x0 - 1 + r;
                bool ok = yok && ((unsigned)p < 256u);
                const char* g = ok ? (srow + (size_t)p * 512) : (const char*)src;
                int sz = ok ? 16 : 0;
                uint32_t d = dst0 + (uint32_t)(t * (32 * ROWW * 4));
                asm volatile("cp.async.cg.shared.global [%0], [%1], 16, %2;"
                             :: "r"(d), "l"(g), "r"(sz));
            }
        }
        asm volatile("cp.async.commit_group;" ::: "memory");
    };

    float c[2][4][4];
#pragma unroll
    for (int fm = 0; fm < 2; ++fm)
#pragma unroll
        for (int fn = 0; fn < 4; ++fn)
#pragma unroll
            for (int t = 0; t < 4; ++t) c[fm][fn][t] = 0.f;

    issueB(0, 0);
    issueB(1, 1);

    for (int j = 0; j < 12; ++j) {
        int sel = j & 1;
        if (j < 11) asm volatile("cp.async.wait_group 1;" ::: "memory");
        else        asm volatile("cp.async.wait_group 0;" ::: "memory");
        __syncthreads();

        const float* Bs = dsm + sel * BSZ;
        int ky = j >> 2, cc = j & 3;
#pragma unroll
        for (int kx = 0; kx < 3; ++kx) {
            const float* Ab = wpack + (size_t)(((ky * 3 + kx) * 4 + cc) * 64) * 32;
#pragma unroll
            for (int ksp = 0; ksp < 2; ++ksp) {
                int colA = lc * 8 + ksp * 4;
                float4 a00 = *(const float4*)&Ab[(warpM * 32 + lr)      * 32 + colA];
                float4 a01 = *(const float4*)&Ab[(warpM * 32 + lr + 8)  * 32 + colA];
                float4 a10 = *(const float4*)&Ab[(warpM * 32 + lr + 16) * 32 + colA];
                float4 a11 = *(const float4*)&Ab[(warpM * 32 + lr + 24) * 32 + colA];
#pragma unroll
                for (int fn = 0; fn < 4; ++fn) {
                    int r = warpN * 32 + fn * 8 + lr + kx;
                    float4 bb = *(const float4*)&Bs[r * ROWW + colA];
                    uint32_t b0 = __float_as_uint(bb.x), b1 = __float_as_uint(bb.y);
                    uint32_t b2 = __float_as_uint(bb.z), b3 = __float_as_uint(bb.w);
                    mma_tf32(c[0][fn], __float_as_uint(a00.x), __float_as_uint(a01.x),
                                       __float_as_uint(a00.y), __float_as_uint(a01.y), b0, b1);
                    mma_tf32(c[1][fn], __float_as_uint(a10.x), __float_as_uint(a11.x),
                                       __float_as_uint(a10.y), __float_as_uint(a11.y), b0, b1);
                    mma_tf32(c[0][fn], __float_as_uint(a00.z), __float_as_uint(a01.z),
                                       __float_as_uint(a00.w), __float_as_uint(a01.w), b2, b3);
                    mma_tf32(c[1][fn], __float_as_uint(a10.z), __float_as_uint(a11.z),
                                       __float_as_uint(a10.w), __float_as_uint(a11.w), b2, b3);
                }
            }
        }
        __syncthreads();                       // all warps done reading buf sel
        if (j + 2 < 12) issueB(j + 2, sel);
    }

    // ---- epilogue: sigmoid -> NCHW match slabs (oc<62) ----
#pragma unroll
    for (int fm = 0; fm < 2; ++fm) {
        int m0 = warpM * 32 + fm * 16 + lr;
        int m1 = m0 + 8;
#pragma unroll
        for (int fn = 0; fn < 4; ++fn) {
            int px = x0 + warpN * 32 + fn * 8 + lc * 2;
            size_t rowoff = (size_t)y * 256 + px;
            if (m0 < 62) {
                size_t base = (m0 < NPAT)
                    ? AM_OFF + ((size_t)(b * NPAT + m0)) * HW
                    : ANM_OFF + ((size_t)(b * NANOM + (m0 - NPAT))) * HW;
                float2 v = make_float2(sigmoidf_(c[fm][fn][0]), sigmoidf_(c[fm][fn][1]));
                *(float2*)&out[base + rowoff] = v;
            }
            if (m1 < 62) {
                size_t base = (m1 < NPAT)
                    ? AM_OFF + ((size_t)(b * NPAT + m1)) * HW
                    : ANM_OFF + ((size_t)(b * NANOM + (m1 - NPAT))) * HW;
                float2 v = make_float2(sigmoidf_(c[fm][fn][2]), sigmoidf_(c[fm][fn][3]));
                *(float2*)&out[base + rowoff] = v;
            }
        }
    }
}

// ---------------------------------------------------------------------------
// bn2 + relu: g_feat NHWC -> d_out features NCHW (fp32) AND writes the
// tf32-rounded CHANNEL-PERMUTED value back to g_feat (matcher input).
// grid (4, 256, BATCH), block 256.
// ---------------------------------------------------------------------------
__global__ void bn2t_kernel(float* __restrict__ out) {
    __shared__ float s_t[64][129];
    __shared__ float s_a[128], s_s[128];
    int tid = threadIdx.x;
    int x0 = blockIdx.x * 64, y = blockIdx.y, b = blockIdx.z;

    if (tid < 128) { s_a[tid] = g_stats2[tid]; s_s[tid] = g_stats2[128 + tid]; }
    __syncthreads();

    float* src = g_feat + ((size_t)(b * 256 + y) * 256 + x0) * 128;
#pragma unroll
    for (int i = 0; i < 32; ++i) {
        int idx = tid + i * 256;
        int px = idx >> 7, ch = idx & 127;
        float v = src[(size_t)px * 128 + ch];
        s_t[px][ch] = fmaxf(fmaf(s_a[ch], v, s_s[ch]), 0.f);
    }
    __syncthreads();
#pragma unroll
    for (int i = 0; i < 32; ++i) {
        int idx = tid + i * 256;
        int px = idx >> 7, ch = idx & 127;
        int k = ch & 31;
        int dst = (ch & ~31) + ((k & 3) * 8 + (k >> 2));
        src[(size_t)px * 128 + dst] = to_tf32(s_t[px][ch]);
    }
#pragma unroll
    for (int i = 0; i < 32; ++i) {
        int idx = tid + i * 256;
        int ch = idx >> 6, px = idx & 63;
        out[FEAT_OFF + ((size_t)(b * 128 + ch)) * HW + (size_t)y * 256 + x0 + px] = s_t[px][ch];
    }
}

// ---------------------------------------------------------------------------
// fused head: per-pixel 190->64 (relu) ->1 (sigmoid) and 190->4 + softmax/sig.
// ALL weights staged once in dynamic smem. 52 KB/CTA.
// ---------------------------------------------------------------------------
__global__ __launch_bounds__(256)
void head_kernel(const float* __restrict__ out_ro,
                 float* __restrict__ out,
                 const float* __restrict__ w1,
                 const float* __restrict__ b1,
                 const float* __restrict__ w2,
                 const float* __restrict__ b2,
                 const float* __restrict__ wc,
                 const float* __restrict__ bc) {
    extern __shared__ float hs[];            // [w1: 190*64][cls: 190*4][w2: 64][b1: 64]
    float* s_w1  = hs;
    float* s_cls = hs + QCIN * 64;
    float* s_w2  = hs + QCIN * 64 + QCIN * 4;
    float* s_b1  = s_w2 + 64;
    int tid = threadIdx.x;

    for (int i = tid; i < QCIN * 64; i += 256) {
        int c = i >> 6, o = i & 63;
        s_w1[i] = w1[o * QCIN + c];
    }
    for (int i = tid; i < QCIN * 4; i += 256) {
        int c = i >> 2, o = i & 3;
        s_cls[i] = wc[o * QCIN + c];
    }
    if (tid < 64) { s_w2[tid] = w2[tid]; s_b1[tid] = b1[tid]; }
    __syncthreads();

    int p = blockIdx.x * 256 + tid;
    int b = p >> 16, pix = p & 65535;

    const float* featp = out_ro + FEAT_OFF + ((size_t)(b * C2)) * HW + pix;
    const float* amp   = out_ro + AM_OFF + ((size_t)(b * NPAT)) * HW + pix;
    const float* anp   = out_ro + ANM_OFF + ((size_t)(b * NANOM)) * HW + pix;

    float acc[64];
#pragma unroll
    for (int o = 0; o < 64; ++o) acc[o] = 0.f;
    float cacc[4] = {0.f, 0.f, 0.f, 0.f};

#pragma unroll 4
    for (int c = 0; c < QCIN; ++c) {
        float v;
        if (c < C2)             v = featp[(size_t)c * HW];
        else if (c < C2 + NPAT) v = amp[(size_t)(c - C2) * HW];
        else                    v = anp[(size_t)(c - C2 - NPAT) * HW];
        const float* wp = &s_w1[c * 64];
#pragma unroll
        for (int o = 0; o < 64; ++o) acc[o] = fmaf(v, wp[o], acc[o]);
        const float* cp = &s_cls[c * 4];
        cacc[0] = fmaf(v, cp[0], cacc[0]);
        cacc[1] = fmaf(v, cp[1], cacc[1]);
        cacc[2] = fmaf(v, cp[2], cacc[2]);
        cacc[3] = fmaf(v, cp[3], cacc[3]);
    }

    float qs = 0.f;
#pragma unroll
    for (int o = 0; o < 64; ++o) {
        float q = fmaxf(acc[o] + s_b1[o], 0.f);
        qs = fmaf(q, s_w2[o], qs);
    }
    float quality = sigmoidf_(qs + b2[0]);

    float c0 = cacc[0] + bc[0];
    float c1 = cacc[1] + bc[1];
    float c2 = cacc[2] + bc[2];
    float c3 = cacc[3] + bc[3];
    float m = fmaxf(c0, fmaxf(c1, c2));
    float e0 = __expf(c0 - m), e1 = __expf(c1 - m), e2 = __expf(c2 - m);
    float inv = 1.f / (e0 + e1 + e2);

    size_t pb = (size_t)b * HW + pix;
    out[RL_OFF + ((size_t)(b * 3)) * HW + pix]     = c0;
    out[RL_OFF + ((size_t)(b * 3 + 1)) * HW + pix] = c1;
    out[RL_OFF + ((size_t)(b * 3 + 2)) * HW + pix] = c2;
    out[AL_OFF + pb] = c3;
    out[QS_OFF + pb] = quality;
    out[RP_OFF + ((size_t)(b * 3)) * HW + pix]     = e0 * inv;
    out[RP_OFF + ((size_t)(b * 3 + 1)) * HW + pix] = e1 * inv;
    out[RP_OFF + ((size_t)(b * 3 + 2)) * HW + pix] = e2 * inv;
    out[AP_OFF + pb] = sigmoidf_(c3);
}

// ---------------------------------------------------------------------------
extern "C" void kernel_launch(void* const* d_in, const int* in_sizes, int n_in,
                              void* d_out, int out_size) {
    (void)in_sizes; (void)n_in; (void)out_size;
    const float* x       = (const float*)d_in[0];
    const float* conv1_w = (const float*)d_in[1];
    const float* conv1_b = (const float*)d_in[2];
    const float* bn1_g   = (const float*)d_in[3];
    const float* bn1_b   = (const float*)d_in[4];
    const float* conv2_w = (const float*)d_in[5];
    const float* conv2_b = (const float*)d_in[6];
    const float* bn2_g   = (const float*)d_in[7];
    const float* bn2_b   = (const float*)d_in[8];
    const float* core_p  = (const float*)d_in[9];
    const float* clad_p  = (const float*)d_in[10];
    const float* ferr_p  = (const float*)d_in[11];
    const float* anom_p  = (const float*)d_in[12];
    const float* qa1_w   = (const float*)d_in[13];
    const float* qa1_b   = (const float*)d_in[14];
    const float* qa2_w   = (const float*)d_in[15];
    const float* qa2_b   = (const float*)d_in[16];
    const float* cls_w   = (const float*)d_in[17];
    const float* cls_b   = (const float*)d_in[18];
    float* out = (float*)d_out;

    const int smem_c2 = 2 * 136 * 36 * 4;           // 39168 (conv2 B double-buffer)
    const int smem_mt = 2 * 136 * 36 * 4;           // 39168 (matcher B double-buffer)
    const int smem_hd = (QCIN * 64 + QCIN * 4 + 128) * 4;   // 52192
    cudaFuncSetAttribute(conv2_kernel,
                         cudaFuncAttributeMaxDynamicSharedMemorySize, smem_c2);
    cudaFuncSetAttribute(matcher_kernel,
                         cudaFuncAttributeMaxDynamicSharedMemorySize, smem_mt);
    cudaFuncSetAttribute(head_kernel,
                         cudaFuncAttributeMaxDynamicSharedMemorySize, smem_hd);

    float* d_stats1; cudaGetSymbolAddress((void**)&d_stats1, g_stats1);
    float* d_stats2; cudaGetSymbolAddress((void**)&d_stats2, g_stats2);
    float* d_h1n;    cudaGetSymbolAddress((void**)&d_h1n, g_h1n);
    float* d_feat;   cudaGetSymbolAddress((void**)&d_feat, g_feat);
    float* d_w2p;    cudaGetSymbolAddress((void**)&d_w2p, g_w2p);
    float* d_mwp;    cudaGetSymbolAddress((void**)&d_mwp, g_mwp);

    // [0] conv1 -> h1 NHWC raw + bn1 stats partials + permuted weight packing
    conv1_kernel<<<dim3(8, 16, 21), 256>>>(x, conv1_w, conv1_b,
                                           conv2_w, core_p, clad_p, ferr_p, anom_p);
    // [1] bn1 affine
    stats_p2v<C1, 512><<<C1, 256>>>(bn1_g, bn1_b, d_stats1);
    // [2] apply bn1+relu+tf32, channel-permuted, in place
    apply1_kernel<<<16384, 256>>>();
    // [3] conv2 shift-reuse tf32 gemm -> g_feat NHWC raw + bn2 partials
    //     <-- ncu profiles my-index 3
    conv2_kernel<<<dim3(2, 256, BATCH), 256, smem_c2>>>(
        d_h1n, d_w2p, conv2_b, d_feat);
    // [4] bn2 affine
    stats_p2v<C2, 2048><<<C2, 256>>>(bn2_g, bn2_b, d_stats2);
    // [5] bn2+relu: NCHW features to d_out + permuted tf32 back to g_feat
    bn2t_kernel<<<dim3(4, 256, BATCH), 256>>>(out);
    // [6] matcher shift-reuse tf32 gemm (NTILE=128, 2048 CTAs) -> AM/ANM
    matcher_kernel<<<dim3(2, 256, BATCH), 256, smem_mt>>>(d_feat, d_mwp, out);
    // [7] fused 1x1 head (single-stage weights) -> remaining 6 output slabs
    head_kernel<<<(BATCH * HW) / 256, 256, smem_hd>>>(
        out, out, qa1_w, qa1_b, qa2_w, qa2_b, cls_w, cls_b);
}

// round 16
// speedup vs baseline: 1.0454x; 1.0454x over previous
#include <cuda_runtime.h>
#include <math.h>
#include <stdint.h>

#define BATCH 4
#define HH 256
#define WW 256
#define HW 65536
#define C1 64
#define C2 128
#define NPAT 30
#define NANOM 32
#define QCIN 190

// d_out element offsets (outputs concatenated in reference return order)
#define FEAT_OFF 0UL
#define RL_OFF   33554432UL
#define AL_OFF   34340864UL
#define AM_OFF   34603008UL
#define ANM_OFF  42467328UL
#define QS_OFF   50855936UL
#define RP_OFF   51118080UL
#define AP_OFF   51904512UL

// ---------------------------------------------------------------------------
// device globals (no allocations allowed)
// ---------------------------------------------------------------------------
__device__ float  g_h1n[BATCH * HW * C1];     // conv1 out NHWC raw; after apply1: tf32(relu(bn1)) ch-permuted
__device__ float  g_feat[BATCH * HW * C2];    // conv2 out NHWC raw; after bn2t: tf32(relu(bn2)) ch-permuted
__device__ float  g_stats1[2 * C1];           // [a | s] affine for bn1
__device__ float  g_stats2[2 * C2];           // [a | s] affine for bn2
__device__ float  g_w2p[9 * 2 * 128 * 32];    // conv2 weights packed, k-permuted, tf32
__device__ float  g_mwp[9 * 4 * 64 * 32];     // matcher weights packed, k-permuted, tf32
__device__ float  g_psumf[128 * 2048];        // stats partials (fp32)
__device__ float  g_psqf[128 * 2048];

__device__ __forceinline__ float sigmoidf_(float v) {
    return 1.f / (1.f + __expf(-v));
}
__device__ __forceinline__ float to_tf32(float v) {
    uint32_t r;
    asm("cvt.rna.tf32.f32 %0, %1;" : "=r"(r) : "f"(v));
    return __uint_as_float(r);
}
__device__ __forceinline__ void mma_tf32(float* c,
                                         uint32_t a0, uint32_t a1, uint32_t a2, uint32_t a3,
                                         uint32_t b0, uint32_t b1) {
    asm volatile(
        "mma.sync.aligned.m16n8k8.row.col.f32.tf32.tf32.f32 "
        "{%0,%1,%2,%3}, {%4,%5,%6,%7}, {%8,%9}, {%0,%1,%2,%3};"
        : "+f"(c[0]), "+f"(c[1]), "+f"(c[2]), "+f"(c[3])
        : "r"(a0), "r"(a1), "r"(a2), "r"(a3), "r"(b0), "r"(b1));
}
// smem col c holds original k = invp(c); perm(k) = (k&3)*8 + (k>>2)
__device__ __forceinline__ int invp(int c) { return (c & 7) * 4 + (c >> 3); }

// ---------------------------------------------------------------------------
// conv1: 3 -> 64, 3x3 pad 1, bias. FFMA, NHWC out (natural channel order).
// z >= 16 planes do k-permuted weight packing instead.
// grid (8, 16, 21), block 256
// ---------------------------------------------------------------------------
__global__ void conv1_kernel(const float* __restrict__ x,
                             const float* __restrict__ w,
                             const float* __restrict__ bias,
                             const float* __restrict__ w2,
                             const float* __restrict__ core,
                             const float* __restrict__ clad,
                             const float* __restrict__ ferr,
                             const float* __restrict__ anom) {
    if (blockIdx.z >= 16) {
        int blk = ((blockIdx.z - 16) * 16 + blockIdx.y) * 8 + blockIdx.x;
        int i = blk * 256 + threadIdx.x;
        if (i < 9 * 2 * 128 * 32) {
            int k = i & 31, oc = (i >> 5) & 127, cc = (i >> 12) & 1, s = i >> 13;
            int ci = cc * 32 + invp(k);
            g_w2p[i] = to_tf32(w2[oc * 576 + ci * 9 + s]);
        } else if (i < 9 * 2 * 128 * 32 + 9 * 4 * 64 * 32) {
            int m = i - 9 * 2 * 128 * 32;
            int k = m & 31, oc = (m >> 5) & 63, cc = (m >> 11) & 3, s = m >> 13;
            int ci = cc * 32 + invp(k);
            float v = 0.f;
            if (oc < 10)      v = core[oc * 1152 + ci * 9 + s];
            else if (oc < 20) v = clad[(oc - 10) * 1152 + ci * 9 + s];
            else if (oc < 30) v = ferr[(oc - 20) * 1152 + ci * 9 + s];
            else if (oc < 62) v = anom[(oc - 30) * 1152 + ci * 9 + s];
            g_mwp[m] = to_tf32(v);
        }
        return;
    }

    __shared__ float s_in[3][18][34];
    __shared__ float s_w[27 * 16];
    __shared__ float s_ps[8][16];
    __shared__ float s_pq[8][16];
    int tid = threadIdx.x;
    int bx = blockIdx.x, by = blockIdx.y;
    int b = blockIdx.z >> 2, g = blockIdx.z & 3;
    int warp = tid >> 5, lane = tid & 31;

    for (int i = tid; i < 3 * 18 * 34; i += 256) {
        int ci = i / 612;
        int r = (i % 612) / 34;
        int c = i % 34;
        int y = by * 16 - 1 + r, xx = bx * 32 - 1 + c;
        float v = 0.f;
        if (y >= 0 && y < HH && xx >= 0 && xx < WW)
            v = x[((size_t)(b * 3 + ci)) * HW + (size_t)y * WW + xx];
        s_in[ci][r][c] = v;
    }
    for (int i = tid; i < 27 * 16; i += 256) {
        int o = i & 15, rest = i >> 4;
        s_w[i] = w[(g * 16 + o) * 27 + rest];
    }
    __syncthreads();

    int tx = tid & 15, ty = tid >> 4;
    float acc0[16], acc1[16];
#pragma unroll
    for (int o = 0; o < 16; ++o) {
        float bb = bias[g * 16 + o];
        acc0[o] = bb; acc1[o] = bb;
    }
#pragma unroll
    for (int ci = 0; ci < 3; ++ci)
#pragma unroll
        for (int k = 0; k < 9; ++k) {
            int ky = k / 3, kx = k % 3;
            float v0 = s_in[ci][ty + ky][tx + kx];
            float v1 = s_in[ci][ty + ky][tx + 16 + kx];
            const float* wp = &s_w[(ci * 9 + k) * 16];
#pragma unroll
            for (int o = 0; o < 16; ++o) {
                float ww = wp[o];
                acc0[o] = fmaf(v0, ww, acc0[o]);
                acc1[o] = fmaf(v1, ww, acc1[o]);
            }
        }
    int gy = by * 16 + ty, gx = bx * 32 + tx;
    size_t p0 = ((size_t)((b * HH + gy) * WW + gx)) * C1 + g * 16;
    size_t p1 = ((size_t)((b * HH + gy) * WW + gx + 16)) * C1 + g * 16;
#pragma unroll
    for (int o = 0; o < 16; ++o) {
        g_h1n[p0 + o] = acc0[o];
        g_h1n[p1 + o] = acc1[o];
    }

#pragma unroll
    for (int o = 0; o < 16; ++o) {
        float s = acc0[o] + acc1[o];
        float q = fmaf(acc0[o], acc0[o], acc1[o] * acc1[o]);
#pragma unroll
        for (int d = 16; d > 0; d >>= 1) {
            s += __shfl_xor_sync(0xffffffffu, s, d);
            q += __shfl_xor_sync(0xffffffffu, q, d);
        }
        if (lane == 0) { s_ps[warp][o] = s; s_pq[warp][o] = q; }
    }
    __syncthreads();
    if (tid < 16) {
        float s = 0.f, q = 0.f;
#pragma unroll
        for (int wp2 = 0; wp2 < 8; ++wp2) { s += s_ps[wp2][tid]; q += s_pq[wp2][tid]; }
        int ch = g * 16 + tid;
        int blk = bx + 8 * (by + 16 * b);
        g_psumf[ch * 512 + blk] = s;
        g_psqf[ch * 512 + blk] = q;
    }
}

// ---------------------------------------------------------------------------
// stats phase 2: reduce NP fp32 partials per channel in double -> affine.
// ---------------------------------------------------------------------------
template<int C, int NP>
__global__ void stats_p2v(const float* __restrict__ gamma,
                          const float* __restrict__ beta,
                          float* __restrict__ statsOut) {
    __shared__ double ss[256], sq[256];
    int c = blockIdx.x, tid = threadIdx.x;
    double s = 0.0, q = 0.0;
#pragma unroll
    for (int k = 0; k < NP / 256; ++k) {
        s += (double)g_psumf[c * NP + tid + k * 256];
        q += (double)g_psqf[c * NP + tid + k * 256];
    }
    ss[tid] = s; sq[tid] = q;
    __syncthreads();
    for (int st = 128; st > 0; st >>= 1) {
        if (tid < st) { ss[tid] += ss[tid + st]; sq[tid] += sq[tid + st]; }
        __syncthreads();
    }
    if (tid == 0) {
        double n = (double)BATCH * (double)HW;
        double mean = ss[0] / n;
        double var = sq[0] / n - mean * mean;
        double a = (double)gamma[c] / sqrt(var + 1e-5);
        statsOut[c] = (float)a;
        statsOut[C + c] = (float)((double)beta[c] - mean * a);
    }
}

// ---------------------------------------------------------------------------
// apply1: g_h1n <- tf32(relu(a*x+s)), channel-PERMUTED within each 32-block,
// in place via smem stage (block owns 16 px x 64 ch). grid 16384, block 256.
// ---------------------------------------------------------------------------
__global__ void apply1_kernel() {
    __shared__ float st[1024];
    int tid = threadIdx.x;
    size_t base = (size_t)blockIdx.x * 1024 + tid * 4;
    int ch0 = (tid * 4) & 63;
    float4 v = *(const float4*)&g_h1n[base];
    v.x = to_tf32(fmaxf(fmaf(g_stats1[ch0 + 0], v.x, g_stats1[C1 + ch0 + 0]), 0.f));
    v.y = to_tf32(fmaxf(fmaf(g_stats1[ch0 + 1], v.y, g_stats1[C1 + ch0 + 1]), 0.f));
    v.z = to_tf32(fmaxf(fmaf(g_stats1[ch0 + 2], v.z, g_stats1[C1 + ch0 + 2]), 0.f));
    v.w = to_tf32(fmaxf(fmaf(g_stats1[ch0 + 3], v.w, g_stats1[C1 + ch0 + 3]), 0.f));
    *(float4*)&st[tid * 4] = v;
    __syncthreads();
    int rowbase = tid * 4 - ch0;
    int blk32 = ch0 & 32;
    int t0 = ch0 & 31;
    float4 o;
    o.x = st[rowbase + blk32 + invp(t0 + 0)];
    o.y = st[rowbase + blk32 + invp(t0 + 1)];
    o.z = st[rowbase + blk32 + invp(t0 + 2)];
    o.w = st[rowbase + blk32 + invp(t0 + 3)];
    *(float4*)&g_h1n[base] = o;
}

// ---------------------------------------------------------------------------
// conv2: shift-reuse tf32 gemm (R14-proven). One B-tile (130 px x 32 ch,
// x-halo) per (ky,cc) serves all 3 kx shifts via shifted smem rows; A read
// directly via LDG from L2-resident packed weights. 6 chunks, 12 barriers.
// Epilogue: +bias -> NHWC g_feat + fused bn2-stats partials.
// grid (2, 256, BATCH), block 256 (warps 4M x 2N, tile 32x64).
// ---------------------------------------------------------------------------
__global__ __launch_bounds__(256, 2)
void conv2_kernel(const float* __restrict__ src,     // g_h1n, tf32 permuted NHWC
                  const float* __restrict__ wpack,   // g_w2p
                  const float* __restrict__ bias,
                  float* __restrict__ out) {         // g_feat NHWC
    constexpr int ROWW = 36;
    constexpr int BROWS = 136;             // rows 0..129 used (r = n + kx, px = x0-1+r)
    constexpr int BSZ = BROWS * ROWW;

    extern __shared__ float dsm[];
    uint32_t sbase = (uint32_t)__cvta_generic_to_shared(dsm);

    int tid = threadIdx.x;
    int warp = tid >> 5, lane = tid & 31;
    int warpM = warp & 3, warpN = warp >> 2;    // 4 x 2
    int lr = lane >> 2, lc = lane & 3;
    int jj = tid & 7;
    int pr = tid >> 3;                          // 0..31
    int x0 = blockIdx.x * 128;
    int y = blockIdx.y, b = blockIdx.z;

    auto issueB = [&](int j, int sel) {
        int ky = j >> 1, cc = j & 1;
        int yy = y + ky - 1;
        bool yok = (unsigned)yy < 256u;
        const char* srow = (const char*)(src
            + ((size_t)((b * 256 + (yok ? yy : 0)) * 256)) * 64 + cc * 32 + jj * 4);
        uint32_t dst0 = sbase + (uint32_t)(sel * (BSZ * 4) + pr * (ROWW * 4) + jj * 16);
#pragma unroll
        for (int t = 0; t < 5; ++t) {
            int r = pr + t * 32;
            if (r < 130) {
                int p = x0 - 1 + r;
                bool ok = yok && ((unsigned)p < 256u);
                const char* g = ok ? (srow + (size_t)p * 256) : (const char*)src;
                int sz = ok ? 16 : 0;
                uint32_t d = dst0 + (uint32_t)(t * (32 * ROWW * 4));
                asm volatile("cp.async.cg.shared.global [%0], [%1], 16, %2;"
                             :: "r"(d), "l"(g), "r"(sz));
            }
        }
        asm volatile("cp.async.commit_group;" ::: "memory");
    };

    float c[2][8][4];
#pragma unroll
    for (int fm = 0; fm < 2; ++fm)
#pragma unroll
        for (int fn = 0; fn < 8; ++fn)
#pragma unroll
            for (int t = 0; t < 4; ++t) c[fm][fn][t] = 0.f;

    issueB(0, 0);
    issueB(1, 1);

    for (int j = 0; j < 6; ++j) {
        int sel = j & 1;
        if (j < 5) asm volatile("cp.async.wait_group 1;" ::: "memory");
        else       asm volatile("cp.async.wait_group 0;" ::: "memory");
        __syncthreads();

        const float* Bs = dsm + sel * BSZ;
        int ky = j >> 1, cc = j & 1;
#pragma unroll
        for (int kx = 0; kx < 3; ++kx) {
            const float* Ab = wpack + (size_t)(((ky * 3 + kx) * 2 + cc) * 128) * 32;
#pragma unroll
            for (int ksp = 0; ksp < 2; ++ksp) {
                int colA = lc * 8 + ksp * 4;
                float4 a00 = *(const float4*)&Ab[(warpM * 32 + lr)      * 32 + colA];
                float4 a01 = *(const float4*)&Ab[(warpM * 32 + lr + 8)  * 32 + colA];
                float4 a10 = *(const float4*)&Ab[(warpM * 32 + lr + 16) * 32 + colA];
                float4 a11 = *(const float4*)&Ab[(warpM * 32 + lr + 24) * 32 + colA];
#pragma unroll
                for (int fn = 0; fn < 8; ++fn) {
                    int r = warpN * 64 + fn * 8 + lr + kx;
                    float4 bb = *(const float4*)&Bs[r * ROWW + colA];
                    uint32_t b0 = __float_as_uint(bb.x), b1 = __float_as_uint(bb.y);
                    uint32_t b2 = __float_as_uint(bb.z), b3 = __float_as_uint(bb.w);
                    mma_tf32(c[0][fn], __float_as_uint(a00.x), __float_as_uint(a01.x),
                                       __float_as_uint(a00.y), __float_as_uint(a01.y), b0, b1);
                    mma_tf32(c[1][fn], __float_as_uint(a10.x), __float_as_uint(a11.x),
                                       __float_as_uint(a10.y), __float_as_uint(a11.y), b0, b1);
                    mma_tf32(c[0][fn], __float_as_uint(a00.z), __float_as_uint(a01.z),
                                       __float_as_uint(a00.w), __float_as_uint(a01.w), b2, b3);
                    mma_tf32(c[1][fn], __float_as_uint(a10.z), __float_as_uint(a11.z),
                                       __float_as_uint(a10.w), __float_as_uint(a11.w), b2, b3);
                }
            }
        }
        __syncthreads();                       // all warps done reading buf sel
        if (j + 2 < 6) issueB(j + 2, sel);
    }

    // ---- epilogue: +bias -> NHWC out + fused bn2-stats partials ----
    {
        __shared__ float s_ps[2][128];
        __shared__ float s_pq[2][128];
        float rs[4], rq[4];
#pragma unroll
        for (int t = 0; t < 4; ++t) { rs[t] = 0.f; rq[t] = 0.f; }
#pragma unroll
        for (int fm = 0; fm < 2; ++fm) {
            int m0 = warpM * 32 + fm * 16 + lr;
            float bv0 = bias[m0], bv1 = bias[m0 + 8];
#pragma unroll
            for (int fn = 0; fn < 8; ++fn) {
                int px = x0 + warpN * 64 + fn * 8 + lc * 2;
                float* p = out + ((size_t)((b * 256 + y) * 256 + px)) * 128;
                float v0 = c[fm][fn][0] + bv0;
                float v1 = c[fm][fn][1] + bv0;
                float v2 = c[fm][fn][2] + bv1;
                float v3 = c[fm][fn][3] + bv1;
                p[m0]           = v0;
                p[128 + m0]     = v1;
                p[m0 + 8]       = v2;
                p[128 + m0 + 8] = v3;
                rs[fm * 2]     += v0 + v1;
                rq[fm * 2]      = fmaf(v0, v0, fmaf(v1, v1, rq[fm * 2]));
                rs[fm * 2 + 1] += v2 + v3;
                rq[fm * 2 + 1]  = fmaf(v2, v2, fmaf(v3, v3, rq[fm * 2 + 1]));
            }
        }
#pragma unroll
        for (int t = 0; t < 4; ++t) {
            rs[t] += __shfl_xor_sync(0xffffffffu, rs[t], 1);
            rs[t] += __shfl_xor_sync(0xffffffffu, rs[t], 2);
            rq[t] += __shfl_xor_sync(0xffffffffu, rq[t], 1);
            rq[t] += __shfl_xor_sync(0xffffffffu, rq[t], 2);
        }
        if (lc == 0) {
#pragma unroll
            for (int t = 0; t < 4; ++t) {
                int row = warpM * 32 + (t >> 1) * 16 + (t & 1) * 8 + lr;
                s_ps[warpN][row] = rs[t];
                s_pq[warpN][row] = rq[t];
            }
        }
        __syncthreads();
        if (tid < 128) {
            float s = s_ps[0][tid] + s_ps[1][tid];
            float q = s_pq[0][tid] + s_pq[1][tid];
            int cta = blockIdx.x + 2 * (blockIdx.y + 256 * blockIdx.z);
            g_psumf[tid * 2048 + cta] = s;
            g_psqf[tid * 2048 + cta] = q;
        }
    }
}

// ---------------------------------------------------------------------------
// matcher: shift-reuse tf32 gemm (R13/R14-proven). One B-tile (258 px x 32 ch)
// per (ky,cc) serves all 3 kx shifts. A via LDG from L2-resident weights.
// grid (256, BATCH), block 256, smem 2*264*36*4 = 76032 B.
// ---------------------------------------------------------------------------
__global__ __launch_bounds__(256, 2)
void matcher_kernel(const float* __restrict__ src,     // g_feat, tf32 permuted NHWC
                    const float* __restrict__ wpack,   // g_mwp
                    float* __restrict__ out) {
    constexpr int ROWW = 36;
    constexpr int BROWS = 264;             // rows 0..257 used (r = n + kx, px = r-1)
    constexpr int BSZ = BROWS * ROWW;

    extern __shared__ float dsm[];
    uint32_t sbase = (uint32_t)__cvta_generic_to_shared(dsm);

    int tid = threadIdx.x;
    int warp = tid >> 5, lane = tid & 31;
    int warpM = warp & 1, warpN = warp >> 1;    // 2 x 4
    int lr = lane >> 2, lc = lane & 3;
    int jj = tid & 7;
    int pr = tid >> 3;                          // 0..31
    int y = blockIdx.x, b = blockIdx.y;

    auto issueB = [&](int j, int sel) {
        int ky = j >> 2, cc = j & 3;
        int yy = y + ky - 1;
        bool yok = (unsigned)yy < 256u;
        const char* srow = (const char*)(src
            + ((size_t)((b * 256 + (yok ? yy : 0)) * 256)) * 128 + cc * 32 + jj * 4);
        uint32_t dst0 = sbase + (uint32_t)(sel * (BSZ * 4) + pr * (ROWW * 4) + jj * 16);
#pragma unroll
        for (int t = 0; t < 9; ++t) {
            int r = pr + t * 32;
            if (r < 258) {
                int p = r - 1;
                bool ok = yok && ((unsigned)p < 256u);
                const char* g = ok ? (srow + (size_t)p * 512) : (const char*)src;
                int sz = ok ? 16 : 0;
                uint32_t d = dst0 + (uint32_t)(t * (32 * ROWW * 4));
                asm volatile("cp.async.cg.shared.global [%0], [%1], 16, %2;"
                             :: "r"(d), "l"(g), "r"(sz));
            }
        }
        asm volatile("cp.async.commit_group;" ::: "memory");
    };

    float c[2][8][4];
#pragma unroll
    for (int fm = 0; fm < 2; ++fm)
#pragma unroll
        for (int fn = 0; fn < 8; ++fn)
#pragma unroll
            for (int t = 0; t < 4; ++t) c[fm][fn][t] = 0.f;

    issueB(0, 0);
    issueB(1, 1);

    for (int j = 0; j < 12; ++j) {
        int sel = j & 1;
        if (j < 11) asm volatile("cp.async.wait_group 1;" ::: "memory");
        else        asm volatile("cp.async.wait_group 0;" ::: "memory");
        __syncthreads();

        const float* Bs = dsm + sel * BSZ;
        int ky = j >> 2, cc = j & 3;
#pragma unroll
        for (int kx = 0; kx < 3; ++kx) {
            const float* Ab = wpack + (size_t)(((ky * 3 + kx) * 4 + cc) * 64) * 32;
#pragma unroll
            for (int ksp = 0; ksp < 2; ++ksp) {
                int colA = lc * 8 + ksp * 4;
                float4 a00 = *(const float4*)&Ab[(warpM * 32 + lr)      * 32 + colA];
                float4 a01 = *(const float4*)&Ab[(warpM * 32 + lr + 8)  * 32 + colA];
                float4 a10 = *(const float4*)&Ab[(warpM * 32 + lr + 16) * 32 + colA];
                float4 a11 = *(const float4*)&Ab[(warpM * 32 + lr + 24) * 32 + colA];
#pragma unroll
                for (int fn = 0; fn < 8; ++fn) {
                    int r = warpN * 64 + fn * 8 + lr + kx;
                    float4 bb = *(const float4*)&Bs[r * ROWW + colA];
                    uint32_t b0 = __float_as_uint(bb.x), b1 = __float_as_uint(bb.y);
                    uint32_t b2 = __float_as_uint(bb.z), b3 = __float_as_uint(bb.w);
                    mma_tf32(c[0][fn], __float_as_uint(a00.x), __float_as_uint(a01.x),
                                       __float_as_uint(a00.y), __float_as_uint(a01.y), b0, b1);
                    mma_tf32(c[1][fn], __float_as_uint(a10.x), __float_as_uint(a11.x),
                                       __float_as_uint(a10.y), __float_as_uint(a11.y), b0, b1);
                    mma_tf32(c[0][fn], __float_as_uint(a00.z), __float_as_uint(a01.z),
                                       __float_as_uint(a00.w), __float_as_uint(a01.w), b2, b3);
                    mma_tf32(c[1][fn], __float_as_uint(a10.z), __float_as_uint(a11.z),
                                       __float_as_uint(a10.w), __float_as_uint(a11.w), b2, b3);
                }
            }
        }
        __syncthreads();                       // all warps done reading buf sel
        if (j + 2 < 12) issueB(j + 2, sel);
    }

    // ---- epilogue: sigmoid -> NCHW match slabs (oc<62) ----
#pragma unroll
    for (int fm = 0; fm < 2; ++fm) {
        int m0 = warpM * 32 + fm * 16 + lr;
        int m1 = m0 + 8;
#pragma unroll
        for (int fn = 0; fn < 8; ++fn) {
            int px = warpN * 64 + fn * 8 + lc * 2;
            size_t rowoff = (size_t)y * 256 + px;
            if (m0 < 62) {
                size_t base = (m0 < NPAT)
                    ? AM_OFF + ((size_t)(b * NPAT + m0)) * HW
                    : ANM_OFF + ((size_t)(b * NANOM + (m0 - NPAT))) * HW;
                float2 v = make_float2(sigmoidf_(c[fm][fn][0]), sigmoidf_(c[fm][fn][1]));
                *(float2*)&out[base + rowoff] = v;
            }
            if (m1 < 62) {
                size_t base = (m1 < NPAT)
                    ? AM_OFF + ((size_t)(b * NPAT + m1)) * HW
                    : ANM_OFF + ((size_t)(b * NANOM + (m1 - NPAT))) * HW;
                float2 v = make_float2(sigmoidf_(c[fm][fn][2]), sigmoidf_(c[fm][fn][3]));
                *(float2*)&out[base + rowoff] = v;
            }
        }
    }
}

// ---------------------------------------------------------------------------
// bn2 + relu: g_feat NHWC -> d_out features NCHW (fp32) AND writes the
// tf32-rounded CHANNEL-PERMUTED value back to g_feat (matcher input).
// grid (4, 256, BATCH), block 256.
// ---------------------------------------------------------------------------
__global__ void bn2t_kernel(float* __restrict__ out) {
    __shared__ float s_t[64][129];
    __shared__ float s_a[128], s_s[128];
    int tid = threadIdx.x;
    int x0 = blockIdx.x * 64, y = blockIdx.y, b = blockIdx.z;

    if (tid < 128) { s_a[tid] = g_stats2[tid]; s_s[tid] = g_stats2[128 + tid]; }
    __syncthreads();

    float* src = g_feat + ((size_t)(b * 256 + y) * 256 + x0) * 128;
#pragma unroll
    for (int i = 0; i < 32; ++i) {
        int idx = tid + i * 256;
        int px = idx >> 7, ch = idx & 127;
        float v = src[(size_t)px * 128 + ch];
        s_t[px][ch] = fmaxf(fmaf(s_a[ch], v, s_s[ch]), 0.f);
    }
    __syncthreads();
#pragma unroll
    for (int i = 0; i < 32; ++i) {
        int idx = tid + i * 256;
        int px = idx >> 7, ch = idx & 127;
        int k = ch & 31;
        int dst = (ch & ~31) + ((k & 3) * 8 + (k >> 2));
        src[(size_t)px * 128 + dst] = to_tf32(s_t[px][ch]);
    }
#pragma unroll
    for (int i = 0; i < 32; ++i) {
        int idx = tid + i * 256;
        int ch = idx >> 6, px = idx & 63;
        out[FEAT_OFF + ((size_t)(b * 128 + ch)) * HW + (size_t)y * 256 + x0 + px] = s_t[px][ch];
    }
}

// ---------------------------------------------------------------------------
// fused head: per-pixel 190->64 (relu) ->1 (sigmoid) and 190->4 + softmax/sig.
// ALL weights staged once in dynamic smem. 52 KB/CTA.
// ---------------------------------------------------------------------------
__global__ __launch_bounds__(256)
void head_kernel(const float* __restrict__ out_ro,
                 float* __restrict__ out,
                 const float* __restrict__ w1,
                 const float* __restrict__ b1,
                 const float* __restrict__ w2,
                 const float* __restrict__ b2,
                 const float* __restrict__ wc,
                 const float* __restrict__ bc) {
    extern __shared__ float hs[];            // [w1: 190*64][cls: 190*4][w2: 64][b1: 64]
    float* s_w1  = hs;
    float* s_cls = hs + QCIN * 64;
    float* s_w2  = hs + QCIN * 64 + QCIN * 4;
    float* s_b1  = s_w2 + 64;
    int tid = threadIdx.x;

    for (int i = tid; i < QCIN * 64; i += 256) {
        int c = i >> 6, o = i & 63;
        s_w1[i] = w1[o * QCIN + c];
    }
    for (int i = tid; i < QCIN * 4; i += 256) {
        int c = i >> 2, o = i & 3;
        s_cls[i] = wc[o * QCIN + c];
    }
    if (tid < 64) { s_w2[tid] = w2[tid]; s_b1[tid] = b1[tid]; }
    __syncthreads();

    int p = blockIdx.x * 256 + tid;
    int b = p >> 16, pix = p & 65535;

    const float* featp = out_ro + FEAT_OFF + ((size_t)(b * C2)) * HW + pix;
    const float* amp   = out_ro + AM_OFF + ((size_t)(b * NPAT)) * HW + pix;
    const float* anp   = out_ro + ANM_OFF + ((size_t)(b * NANOM)) * HW + pix;

    float acc[64];
#pragma unroll
    for (int o = 0; o < 64; ++o) acc[o] = 0.f;
    float cacc[4] = {0.f, 0.f, 0.f, 0.f};

#pragma unroll 4
    for (int c = 0; c < QCIN; ++c) {
        float v;
        if (c < C2)             v = featp[(size_t)c * HW];
        else if (c < C2 + NPAT) v = amp[(size_t)(c - C2) * HW];
        else                    v = anp[(size_t)(c - C2 - NPAT) * HW];
        const float* wp = &s_w1[c * 64];
#pragma unroll
        for (int o = 0; o < 64; ++o) acc[o] = fmaf(v, wp[o], acc[o]);
        const float* cp = &s_cls[c * 4];
        cacc[0] = fmaf(v, cp[0], cacc[0]);
        cacc[1] = fmaf(v, cp[1], cacc[1]);
        cacc[2] = fmaf(v, cp[2], cacc[2]);
        cacc[3] = fmaf(v, cp[3], cacc[3]);
    }

    float qs = 0.f;
#pragma unroll
    for (int o = 0; o < 64; ++o) {
        float q = fmaxf(acc[o] + s_b1[o], 0.f);
        qs = fmaf(q, s_w2[o], qs);
    }
    float quality = sigmoidf_(qs + b2[0]);

    float c0 = cacc[0] + bc[0];
    float c1 = cacc[1] + bc[1];
    float c2 = cacc[2] + bc[2];
    float c3 = cacc[3] + bc[3];
    float m = fmaxf(c0, fmaxf(c1, c2));
    float e0 = __expf(c0 - m), e1 = __expf(c1 - m), e2 = __expf(c2 - m);
    float inv = 1.f / (e0 + e1 + e2);

    size_t pb = (size_t)b * HW + pix;
    out[RL_OFF + ((size_t)(b * 3)) * HW + pix]     = c0;
    out[RL_OFF + ((size_t)(b * 3 + 1)) * HW + pix] = c1;
    out[RL_OFF + ((size_t)(b * 3 + 2)) * HW + pix] = c2;
    out[AL_OFF + pb] = c3;
    out[QS_OFF + pb] = quality;
    out[RP_OFF + ((size_t)(b * 3)) * HW + pix]     = e0 * inv;
    out[RP_OFF + ((size_t)(b * 3 + 1)) * HW + pix] = e1 * inv;
    out[RP_OFF + ((size_t)(b * 3 + 2)) * HW + pix] = e2 * inv;
    out[AP_OFF + pb] = sigmoidf_(c3);
}

// ---------------------------------------------------------------------------
extern "C" void kernel_launch(void* const* d_in, const int* in_sizes, int n_in,
                              void* d_out, int out_size) {
    (void)in_sizes; (void)n_in; (void)out_size;
    const float* x       = (const float*)d_in[0];
    const float* conv1_w = (const float*)d_in[1];
    const float* conv1_b = (const float*)d_in[2];
    const float* bn1_g   = (const float*)d_in[3];
    const float* bn1_b   = (const float*)d_in[4];
    const float* conv2_w = (const float*)d_in[5];
    const float* conv2_b = (const float*)d_in[6];
    const float* bn2_g   = (const float*)d_in[7];
    const float* bn2_b   = (const float*)d_in[8];
    const float* core_p  = (const float*)d_in[9];
    const float* clad_p  = (const float*)d_in[10];
    const float* ferr_p  = (const float*)d_in[11];
    const float* anom_p  = (const float*)d_in[12];
    const float* qa1_w   = (const float*)d_in[13];
    const float* qa1_b   = (const float*)d_in[14];
    const float* qa2_w   = (const float*)d_in[15];
    const float* qa2_b   = (const float*)d_in[16];
    const float* cls_w   = (const float*)d_in[17];
    const float* cls_b   = (const float*)d_in[18];
    float* out = (float*)d_out;

    const int smem_c2 = 2 * 136 * 36 * 4;           // 39168 (conv2 B double-buffer)
    const int smem_mt = 2 * 264 * 36 * 4;           // 76032 (matcher B double-buffer)
    const int smem_hd = (QCIN * 64 + QCIN * 4 + 128) * 4;   // 52192
    cudaFuncSetAttribute(conv2_kernel,
                         cudaFuncAttributeMaxDynamicSharedMemorySize, smem_c2);
    cudaFuncSetAttribute(matcher_kernel,
                         cudaFuncAttributeMaxDynamicSharedMemorySize, smem_mt);
    cudaFuncSetAttribute(head_kernel,
                         cudaFuncAttributeMaxDynamicSharedMemorySize, smem_hd);

    float* d_stats1; cudaGetSymbolAddress((void**)&d_stats1, g_stats1);
    float* d_stats2; cudaGetSymbolAddress((void**)&d_stats2, g_stats2);
    float* d_h1n;    cudaGetSymbolAddress((void**)&d_h1n, g_h1n);
    float* d_feat;   cudaGetSymbolAddress((void**)&d_feat, g_feat);
    float* d_w2p;    cudaGetSymbolAddress((void**)&d_w2p, g_w2p);
    float* d_mwp;    cudaGetSymbolAddress((void**)&d_mwp, g_mwp);

    // [0] conv1 -> h1 NHWC raw + bn1 stats partials + permuted weight packing
    conv1_kernel<<<dim3(8, 16, 21), 256>>>(x, conv1_w, conv1_b,
                                           conv2_w, core_p, clad_p, ferr_p, anom_p);
    // [1] bn1 affine
    stats_p2v<C1, 512><<<C1, 256>>>(bn1_g, bn1_b, d_stats1);
    // [2] apply bn1+relu+tf32, channel-permuted, in place
    apply1_kernel<<<16384, 256>>>();
    // [3] conv2 shift-reuse tf32 gemm -> g_feat NHWC raw + bn2 partials
    conv2_kernel<<<dim3(2, 256, BATCH), 256, smem_c2>>>(
        d_h1n, d_w2p, conv2_b, d_feat);
    // [4] bn2 affine
    stats_p2v<C2, 2048><<<C2, 256>>>(bn2_g, bn2_b, d_stats2);
    // [5] bn2+relu: NCHW features to d_out + permuted tf32 back to g_feat
    bn2t_kernel<<<dim3(4, 256, BATCH), 256>>>(out);
    // [6] matcher shift-reuse tf32 gemm (NTILE=256) -> AM/ANM slabs
    matcher_kernel<<<dim3(256, BATCH), 256, smem_mt>>>(d_feat, d_mwp, out);
    // [7] fused 1x1 head (single-stage weights) -> remaining 6 output slabs
    head_kernel<<<(BATCH * HW) / 256, 256, smem_hd>>>(
        out, out, qa1_w, qa1_b, qa2_w, qa2_b, cls_w, cls_b);
}

// round 17
// speedup vs baseline: 1.0624x; 1.0163x over previous
#include <cuda_runtime.h>
#include <math.h>
#include <stdint.h>

#define BATCH 4
#define HH 256
#define WW 256
#define HW 65536
#define C1 64
#define C2 128
#define NPAT 30
#define NANOM 32
#define QCIN 190

// d_out element offsets (outputs concatenated in reference return order)
#define FEAT_OFF 0UL
#define RL_OFF   33554432UL
#define AL_OFF   34340864UL
#define AM_OFF   34603008UL
#define ANM_OFF  42467328UL
#define QS_OFF   50855936UL
#define RP_OFF   51118080UL
#define AP_OFF   51904512UL

// ---------------------------------------------------------------------------
// device globals (no allocations allowed)
// ---------------------------------------------------------------------------
__device__ float  g_h1n[BATCH * HW * C1];     // conv1 out NHWC raw; after apply1: tf32(relu(bn1)) ch-permuted
__device__ float  g_feat[BATCH * HW * C2];    // conv2 out NHWC raw; after bn2t: tf32(relu(bn2)) ch-permuted
__device__ float  g_stats1[2 * C1];           // [a | s] affine for bn1
__device__ float  g_stats2[2 * C2];           // [a | s] affine for bn2
__device__ float  g_w2p[9 * 2 * 128 * 32];    // conv2 weights packed, k-permuted, tf32
__device__ float  g_mwp[9 * 4 * 64 * 32];     // matcher weights packed, k-permuted, tf32
__device__ float  g_psumf[128 * 2048];        // stats partials (fp32)
__device__ float  g_psqf[128 * 2048];

__device__ __forceinline__ float sigmoidf_(float v) {
    return 1.f / (1.f + __expf(-v));
}
__device__ __forceinline__ float to_tf32(float v) {
    uint32_t r;
    asm("cvt.rna.tf32.f32 %0, %1;" : "=r"(r) : "f"(v));
    return __uint_as_float(r);
}
__device__ __forceinline__ void mma_tf32(float* c,
                                         uint32_t a0, uint32_t a1, uint32_t a2, uint32_t a3,
                                         uint32_t b0, uint32_t b1) {
    asm volatile(
        "mma.sync.aligned.m16n8k8.row.col.f32.tf32.tf32.f32 "
        "{%0,%1,%2,%3}, {%4,%5,%6,%7}, {%8,%9}, {%0,%1,%2,%3};"
        : "+f"(c[0]), "+f"(c[1]), "+f"(c[2]), "+f"(c[3])
        : "r"(a0), "r"(a1), "r"(a2), "r"(a3), "r"(b0), "r"(b1));
}
// smem col c holds original k = invp(c); perm(k) = (k&3)*8 + (k>>2)
__device__ __forceinline__ int invp(int c) { return (c & 7) * 4 + (c >> 3); }

// ---------------------------------------------------------------------------
// conv1: 3 -> 64, 3x3 pad 1, bias. FFMA, NHWC out (natural channel order).
// z >= 16 planes do k-permuted weight packing instead.
// grid (8, 16, 21), block 256
// ---------------------------------------------------------------------------
__global__ void conv1_kernel(const float* __restrict__ x,
                             const float* __restrict__ w,
                             const float* __restrict__ bias,
                             const float* __restrict__ w2,
                             const float* __restrict__ core,
                             const float* __restrict__ clad,
                             const float* __restrict__ ferr,
                             const float* __restrict__ anom) {
    if (blockIdx.z >= 16) {
        int blk = ((blockIdx.z - 16) * 16 + blockIdx.y) * 8 + blockIdx.x;
        int i = blk * 256 + threadIdx.x;
        if (i < 9 * 2 * 128 * 32) {
            int k = i & 31, oc = (i >> 5) & 127, cc = (i >> 12) & 1, s = i >> 13;
            int ci = cc * 32 + invp(k);
            g_w2p[i] = to_tf32(w2[oc * 576 + ci * 9 + s]);
        } else if (i < 9 * 2 * 128 * 32 + 9 * 4 * 64 * 32) {
            int m = i - 9 * 2 * 128 * 32;
            int k = m & 31, oc = (m >> 5) & 63, cc = (m >> 11) & 3, s = m >> 13;
            int ci = cc * 32 + invp(k);
            float v = 0.f;
            if (oc < 10)      v = core[oc * 1152 + ci * 9 + s];
            else if (oc < 20) v = clad[(oc - 10) * 1152 + ci * 9 + s];
            else if (oc < 30) v = ferr[(oc - 20) * 1152 + ci * 9 + s];
            else if (oc < 62) v = anom[(oc - 30) * 1152 + ci * 9 + s];
            g_mwp[m] = to_tf32(v);
        }
        return;
    }

    __shared__ float s_in[3][18][34];
    __shared__ float s_w[27 * 16];
    __shared__ float s_ps[8][16];
    __shared__ float s_pq[8][16];
    int tid = threadIdx.x;
    int bx = blockIdx.x, by = blockIdx.y;
    int b = blockIdx.z >> 2, g = blockIdx.z & 3;
    int warp = tid >> 5, lane = tid & 31;

    for (int i = tid; i < 3 * 18 * 34; i += 256) {
        int ci = i / 612;
        int r = (i % 612) / 34;
        int c = i % 34;
        int y = by * 16 - 1 + r, xx = bx * 32 - 1 + c;
        float v = 0.f;
        if (y >= 0 && y < HH && xx >= 0 && xx < WW)
            v = x[((size_t)(b * 3 + ci)) * HW + (size_t)y * WW + xx];
        s_in[ci][r][c] = v;
    }
    for (int i = tid; i < 27 * 16; i += 256) {
        int o = i & 15, rest = i >> 4;
        s_w[i] = w[(g * 16 + o) * 27 + rest];
    }
    __syncthreads();

    int tx = tid & 15, ty = tid >> 4;
    float acc0[16], acc1[16];
#pragma unroll
    for (int o = 0; o < 16; ++o) {
        float bb = bias[g * 16 + o];
        acc0[o] = bb; acc1[o] = bb;
    }
#pragma unroll
    for (int ci = 0; ci < 3; ++ci)
#pragma unroll
        for (int k = 0; k < 9; ++k) {
            int ky = k / 3, kx = k % 3;
            float v0 = s_in[ci][ty + ky][tx + kx];
            float v1 = s_in[ci][ty + ky][tx + 16 + kx];
            const float* wp = &s_w[(ci * 9 + k) * 16];
#pragma unroll
            for (int o = 0; o < 16; ++o) {
                float ww = wp[o];
                acc0[o] = fmaf(v0, ww, acc0[o]);
                acc1[o] = fmaf(v1, ww, acc1[o]);
            }
        }
    int gy = by * 16 + ty, gx = bx * 32 + tx;
    size_t p0 = ((size_t)((b * HH + gy) * WW + gx)) * C1 + g * 16;
    size_t p1 = ((size_t)((b * HH + gy) * WW + gx + 16)) * C1 + g * 16;
#pragma unroll
    for (int o = 0; o < 16; ++o) {
        g_h1n[p0 + o] = acc0[o];
        g_h1n[p1 + o] = acc1[o];
    }

#pragma unroll
    for (int o = 0; o < 16; ++o) {
        float s = acc0[o] + acc1[o];
        float q = fmaf(acc0[o], acc0[o], acc1[o] * acc1[o]);
#pragma unroll
        for (int d = 16; d > 0; d >>= 1) {
            s += __shfl_xor_sync(0xffffffffu, s, d);
            q += __shfl_xor_sync(0xffffffffu, q, d);
        }
        if (lane == 0) { s_ps[warp][o] = s; s_pq[warp][o] = q; }
    }
    __syncthreads();
    if (tid < 16) {
        float s = 0.f, q = 0.f;
#pragma unroll
        for (int wp2 = 0; wp2 < 8; ++wp2) { s += s_ps[wp2][tid]; q += s_pq[wp2][tid]; }
        int ch = g * 16 + tid;
        int blk = bx + 8 * (by + 16 * b);
        g_psumf[ch * 512 + blk] = s;
        g_psqf[ch * 512 + blk] = q;
    }
}

// ---------------------------------------------------------------------------
// stats phase 2: reduce NP fp32 partials per channel in double -> affine.
// ---------------------------------------------------------------------------
template<int C, int NP>
__global__ void stats_p2v(const float* __restrict__ gamma,
                          const float* __restrict__ beta,
                          float* __restrict__ statsOut) {
    __shared__ double ss[256], sq[256];
    int c = blockIdx.x, tid = threadIdx.x;
    double s = 0.0, q = 0.0;
#pragma unroll
    for (int k = 0; k < NP / 256; ++k) {
        s += (double)g_psumf[c * NP + tid + k * 256];
        q += (double)g_psqf[c * NP + tid + k * 256];
    }
    ss[tid] = s; sq[tid] = q;
    __syncthreads();
    for (int st = 128; st > 0; st >>= 1) {
        if (tid < st) { ss[tid] += ss[tid + st]; sq[tid] += sq[tid + st]; }
        __syncthreads();
    }
    if (tid == 0) {
        double n = (double)BATCH * (double)HW;
        double mean = ss[0] / n;
        double var = sq[0] / n - mean * mean;
        double a = (double)gamma[c] / sqrt(var + 1e-5);
        statsOut[c] = (float)a;
        statsOut[C + c] = (float)((double)beta[c] - mean * a);
    }
}

// ---------------------------------------------------------------------------
// apply1: g_h1n <- tf32(relu(a*x+s)), channel-PERMUTED within each 32-block,
// in place via smem stage (block owns 16 px x 64 ch). grid 16384, block 256.
// ---------------------------------------------------------------------------
__global__ void apply1_kernel() {
    __shared__ float st[1024];
    int tid = threadIdx.x;
    size_t base = (size_t)blockIdx.x * 1024 + tid * 4;
    int ch0 = (tid * 4) & 63;
    float4 v = *(const float4*)&g_h1n[base];
    v.x = to_tf32(fmaxf(fmaf(g_stats1[ch0 + 0], v.x, g_stats1[C1 + ch0 + 0]), 0.f));
    v.y = to_tf32(fmaxf(fmaf(g_stats1[ch0 + 1], v.y, g_stats1[C1 + ch0 + 1]), 0.f));
    v.z = to_tf32(fmaxf(fmaf(g_stats1[ch0 + 2], v.z, g_stats1[C1 + ch0 + 2]), 0.f));
    v.w = to_tf32(fmaxf(fmaf(g_stats1[ch0 + 3], v.w, g_stats1[C1 + ch0 + 3]), 0.f));
    *(float4*)&st[tid * 4] = v;
    __syncthreads();
    int rowbase = tid * 4 - ch0;
    int blk32 = ch0 & 32;
    int t0 = ch0 & 31;
    float4 o;
    o.x = st[rowbase + blk32 + invp(t0 + 0)];
    o.y = st[rowbase + blk32 + invp(t0 + 1)];
    o.z = st[rowbase + blk32 + invp(t0 + 2)];
    o.w = st[rowbase + blk32 + invp(t0 + 3)];
    *(float4*)&g_h1n[base] = o;
}

// ---------------------------------------------------------------------------
// conv2: shift-reuse tf32 gemm, 3-STAGE B pipeline (one barrier per chunk).
// One B-tile (130 px x 32 ch, x-halo) per (ky,cc) serves all 3 kx shifts via
// shifted smem rows; A read directly via LDG from L2-resident packed weights.
// issueB(j+2) after compute targets buffer (j+2)%3, last read at chunk j-1 —
// the start-of-chunk-j barrier proves those reads are done. 6 barriers/CTA.
// Epilogue: +bias -> NHWC g_feat + fused bn2-stats partials.
// grid (2, 256, BATCH), block 256 (warps 4M x 2N, tile 32x64). smem 58.8KB.
// ---------------------------------------------------------------------------
__global__ __launch_bounds__(256, 2)
void conv2_kernel(const float* __restrict__ src,     // g_h1n, tf32 permuted NHWC
                  const float* __restrict__ wpack,   // g_w2p
                  const float* __restrict__ bias,
                  float* __restrict__ out) {         // g_feat NHWC
    constexpr int ROWW = 36;
    constexpr int BROWS = 136;             // rows 0..129 used (r = n + kx, px = x0-1+r)
    constexpr int BSZ = BROWS * ROWW;

    extern __shared__ float dsm[];
    uint32_t sbase = (uint32_t)__cvta_generic_to_shared(dsm);

    int tid = threadIdx.x;
    int warp = tid >> 5, lane = tid & 31;
    int warpM = warp & 3, warpN = warp >> 2;    // 4 x 2
    int lr = lane >> 2, lc = lane & 3;
    int jj = tid & 7;
    int pr = tid >> 3;                          // 0..31
    int x0 = blockIdx.x * 128;
    int y = blockIdx.y, b = blockIdx.z;

    auto issueB = [&](int j, int sel) {
        int ky = j >> 1, cc = j & 1;
        int yy = y + ky - 1;
        bool yok = (unsigned)yy < 256u;
        const char* srow = (const char*)(src
            + ((size_t)((b * 256 + (yok ? yy : 0)) * 256)) * 64 + cc * 32 + jj * 4);
        uint32_t dst0 = sbase + (uint32_t)(sel * (BSZ * 4) + pr * (ROWW * 4) + jj * 16);
#pragma unroll
        for (int t = 0; t < 5; ++t) {
            int r = pr + t * 32;
            if (r < 130) {
                int p = x0 - 1 + r;
                bool ok = yok && ((unsigned)p < 256u);
                const char* g = ok ? (srow + (size_t)p * 256) : (const char*)src;
                int sz = ok ? 16 : 0;
                uint32_t d = dst0 + (uint32_t)(t * (32 * ROWW * 4));
                asm volatile("cp.async.cg.shared.global [%0], [%1], 16, %2;"
                             :: "r"(d), "l"(g), "r"(sz));
            }
        }
        asm volatile("cp.async.commit_group;" ::: "memory");
    };

    float c[2][8][4];
#pragma unroll
    for (int fm = 0; fm < 2; ++fm)
#pragma unroll
        for (int fn = 0; fn < 8; ++fn)
#pragma unroll
            for (int t = 0; t < 4; ++t) c[fm][fn][t] = 0.f;

    issueB(0, 0);
    issueB(1, 1);

    auto step = [&](int j, int sel) {
        if (j < 5) asm volatile("cp.async.wait_group 1;" ::: "memory");
        else       asm volatile("cp.async.wait_group 0;" ::: "memory");
        __syncthreads();

        const float* Bs = dsm + sel * BSZ;
        int ky = j >> 1, cc = j & 1;
#pragma unroll
        for (int kx = 0; kx < 3; ++kx) {
            const float* Ab = wpack + (size_t)(((ky * 3 + kx) * 2 + cc) * 128) * 32;
#pragma unroll
            for (int ksp = 0; ksp < 2; ++ksp) {
                int colA = lc * 8 + ksp * 4;
                float4 a00 = *(const float4*)&Ab[(warpM * 32 + lr)      * 32 + colA];
                float4 a01 = *(const float4*)&Ab[(warpM * 32 + lr + 8)  * 32 + colA];
                float4 a10 = *(const float4*)&Ab[(warpM * 32 + lr + 16) * 32 + colA];
                float4 a11 = *(const float4*)&Ab[(warpM * 32 + lr + 24) * 32 + colA];
#pragma unroll
                for (int fn = 0; fn < 8; ++fn) {
                    int r = warpN * 64 + fn * 8 + lr + kx;
                    float4 bb = *(const float4*)&Bs[r * ROWW + colA];
                    uint32_t b0 = __float_as_uint(bb.x), b1 = __float_as_uint(bb.y);
                    uint32_t b2 = __float_as_uint(bb.z), b3 = __float_as_uint(bb.w);
                    mma_tf32(c[0][fn], __float_as_uint(a00.x), __float_as_uint(a01.x),
                                       __float_as_uint(a00.y), __float_as_uint(a01.y), b0, b1);
                    mma_tf32(c[1][fn], __float_as_uint(a10.x), __float_as_uint(a11.x),
                                       __float_as_uint(a10.y), __float_as_uint(a11.y), b0, b1);
                    mma_tf32(c[0][fn], __float_as_uint(a00.z), __float_as_uint(a01.z),
                                       __float_as_uint(a00.w), __float_as_uint(a01.w), b2, b3);
                    mma_tf32(c[1][fn], __float_as_uint(a10.z), __float_as_uint(a11.z),
                                       __float_as_uint(a10.w), __float_as_uint(a11.w), b2, b3);
                }
            }
        }
        // 3-stage: buffer (j+2)%3 was last read at chunk j-1; the barrier at
        // the top of this chunk proves all warps finished it. No second sync.
        if (j + 2 < 6) issueB(j + 2, (j + 2) % 3);
    };

    step(0, 0); step(1, 1); step(2, 2);
    step(3, 0); step(4, 1); step(5, 2);

    // ---- epilogue: +bias -> NHWC out + fused bn2-stats partials ----
    {
        __shared__ float s_ps[2][128];
        __shared__ float s_pq[2][128];
        float rs[4], rq[4];
#pragma unroll
        for (int t = 0; t < 4; ++t) { rs[t] = 0.f; rq[t] = 0.f; }
#pragma unroll
        for (int fm = 0; fm < 2; ++fm) {
            int m0 = warpM * 32 + fm * 16 + lr;
            float bv0 = bias[m0], bv1 = bias[m0 + 8];
#pragma unroll
            for (int fn = 0; fn < 8; ++fn) {
                int px = x0 + warpN * 64 + fn * 8 + lc * 2;
                float* p = out + ((size_t)((b * 256 + y) * 256 + px)) * 128;
                float v0 = c[fm][fn][0] + bv0;
                float v1 = c[fm][fn][1] + bv0;
                float v2 = c[fm][fn][2] + bv1;
                float v3 = c[fm][fn][3] + bv1;
                p[m0]           = v0;
                p[128 + m0]     = v1;
                p[m0 + 8]       = v2;
                p[128 + m0 + 8] = v3;
                rs[fm * 2]     += v0 + v1;
                rq[fm * 2]      = fmaf(v0, v0, fmaf(v1, v1, rq[fm * 2]));
                rs[fm * 2 + 1] += v2 + v3;
                rq[fm * 2 + 1]  = fmaf(v2, v2, fmaf(v3, v3, rq[fm * 2 + 1]));
            }
        }
#pragma unroll
        for (int t = 0; t < 4; ++t) {
            rs[t] += __shfl_xor_sync(0xffffffffu, rs[t], 1);
            rs[t] += __shfl_xor_sync(0xffffffffu, rs[t], 2);
            rq[t] += __shfl_xor_sync(0xffffffffu, rq[t], 1);
            rq[t] += __shfl_xor_sync(0xffffffffu, rq[t], 2);
        }
        if (lc == 0) {
#pragma unroll
            for (int t = 0; t < 4; ++t) {
                int row = warpM * 32 + (t >> 1) * 16 + (t & 1) * 8 + lr;
                s_ps[warpN][row] = rs[t];
                s_pq[warpN][row] = rq[t];
            }
        }
        __syncthreads();
        if (tid < 128) {
            float s = s_ps[0][tid] + s_ps[1][tid];
            float q = s_pq[0][tid] + s_pq[1][tid];
            int cta = blockIdx.x + 2 * (blockIdx.y + 256 * blockIdx.z);
            g_psumf[tid * 2048 + cta] = s;
            g_psqf[tid * 2048 + cta] = q;
        }
    }
}

// ---------------------------------------------------------------------------
// matcher: shift-reuse tf32 gemm (R13/R14-proven). One B-tile (258 px x 32 ch)
// per (ky,cc) serves all 3 kx shifts. A via LDG from L2-resident weights.
// grid (256, BATCH), block 256, smem 2*264*36*4 = 76032 B.
// ---------------------------------------------------------------------------
__global__ __launch_bounds__(256, 2)
void matcher_kernel(const float* __restrict__ src,     // g_feat, tf32 permuted NHWC
                    const float* __restrict__ wpack,   // g_mwp
                    float* __restrict__ out) {
    constexpr int ROWW = 36;
    constexpr int BROWS = 264;             // rows 0..257 used (r = n + kx, px = r-1)
    constexpr int BSZ = BROWS * ROWW;

    extern __shared__ float dsm[];
    uint32_t sbase = (uint32_t)__cvta_generic_to_shared(dsm);

    int tid = threadIdx.x;
    int warp = tid >> 5, lane = tid & 31;
    int warpM = warp & 1, warpN = warp >> 1;    // 2 x 4
    int lr = lane >> 2, lc = lane & 3;
    int jj = tid & 7;
    int pr = tid >> 3;                          // 0..31
    int y = blockIdx.x, b = blockIdx.y;

    auto issueB = [&](int j, int sel) {
        int ky = j >> 2, cc = j & 3;
        int yy = y + ky - 1;
        bool yok = (unsigned)yy < 256u;
        const char* srow = (const char*)(src
            + ((size_t)((b * 256 + (yok ? yy : 0)) * 256)) * 128 + cc * 32 + jj * 4);
        uint32_t dst0 = sbase + (uint32_t)(sel * (BSZ * 4) + pr * (ROWW * 4) + jj * 16);
#pragma unroll
        for (int t = 0; t < 9; ++t) {
            int r = pr + t * 32;
            if (r < 258) {
                int p = r - 1;
                bool ok = yok && ((unsigned)p < 256u);
                const char* g = ok ? (srow + (size_t)p * 512) : (const char*)src;
                int sz = ok ? 16 : 0;
                uint32_t d = dst0 + (uint32_t)(t * (32 * ROWW * 4));
                asm volatile("cp.async.cg.shared.global [%0], [%1], 16, %2;"
                             :: "r"(d), "l"(g), "r"(sz));
            }
        }
        asm volatile("cp.async.commit_group;" ::: "memory");
    };

    float c[2][8][4];
#pragma unroll
    for (int fm = 0; fm < 2; ++fm)
#pragma unroll
        for (int fn = 0; fn < 8; ++fn)
#pragma unroll
            for (int t = 0; t < 4; ++t) c[fm][fn][t] = 0.f;

    issueB(0, 0);
    issueB(1, 1);

    for (int j = 0; j < 12; ++j) {
        int sel = j & 1;
        if (j < 11) asm volatile("cp.async.wait_group 1;" ::: "memory");
        else        asm volatile("cp.async.wait_group 0;" ::: "memory");
        __syncthreads();

        const float* Bs = dsm + sel * BSZ;
        int ky = j >> 2, cc = j & 3;
#pragma unroll
        for (int kx = 0; kx < 3; ++kx) {
            const float* Ab = wpack + (size_t)(((ky * 3 + kx) * 4 + cc) * 64) * 32;
#pragma unroll
            for (int ksp = 0; ksp < 2; ++ksp) {
                int colA = lc * 8 + ksp * 4;
                float4 a00 = *(const float4*)&Ab[(warpM * 32 + lr)      * 32 + colA];
                float4 a01 = *(const float4*)&Ab[(warpM * 32 + lr + 8)  * 32 + colA];
                float4 a10 = *(const float4*)&Ab[(warpM * 32 + lr + 16) * 32 + colA];
                float4 a11 = *(const float4*)&Ab[(warpM * 32 + lr + 24) * 32 + colA];
#pragma unroll
                for (int fn = 0; fn < 8; ++fn) {
                    int r = warpN * 64 + fn * 8 + lr + kx;
                    float4 bb = *(const float4*)&Bs[r * ROWW + colA];
                    uint32_t b0 = __float_as_uint(bb.x), b1 = __float_as_uint(bb.y);
                    uint32_t b2 = __float_as_uint(bb.z), b3 = __float_as_uint(bb.w);
                    mma_tf32(c[0][fn], __float_as_uint(a00.x), __float_as_uint(a01.x),
                                       __float_as_uint(a00.y), __float_as_uint(a01.y), b0, b1);
                    mma_tf32(c[1][fn], __float_as_uint(a10.x), __float_as_uint(a11.x),
                                       __float_as_uint(a10.y), __float_as_uint(a11.y), b0, b1);
                    mma_tf32(c[0][fn], __float_as_uint(a00.z), __float_as_uint(a01.z),
                                       __float_as_uint(a00.w), __float_as_uint(a01.w), b2, b3);
                    mma_tf32(c[1][fn], __float_as_uint(a10.z), __float_as_uint(a11.z),
                                       __float_as_uint(a10.w), __float_as_uint(a11.w), b2, b3);
                }
            }
        }
        __syncthreads();                       // all warps done reading buf sel
        if (j + 2 < 12) issueB(j + 2, sel);
    }

    // ---- epilogue: sigmoid -> NCHW match slabs (oc<62) ----
#pragma unroll
    for (int fm = 0; fm < 2; ++fm) {
        int m0 = warpM * 32 + fm * 16 + lr;
        int m1 = m0 + 8;
#pragma unroll
        for (int fn = 0; fn < 8; ++fn) {
            int px = warpN * 64 + fn * 8 + lc * 2;
            size_t rowoff = (size_t)y * 256 + px;
            if (m0 < 62) {
                size_t base = (m0 < NPAT)
                    ? AM_OFF + ((size_t)(b * NPAT + m0)) * HW
                    : ANM_OFF + ((size_t)(b * NANOM + (m0 - NPAT))) * HW;
                float2 v = make_float2(sigmoidf_(c[fm][fn][0]), sigmoidf_(c[fm][fn][1]));
                *(float2*)&out[base + rowoff] = v;
            }
            if (m1 < 62) {
                size_t base = (m1 < NPAT)
                    ? AM_OFF + ((size_t)(b * NPAT + m1)) * HW
                    : ANM_OFF + ((size_t)(b * NANOM + (m1 - NPAT))) * HW;
                float2 v = make_float2(sigmoidf_(c[fm][fn][2]), sigmoidf_(c[fm][fn][3]));
                *(float2*)&out[base + rowoff] = v;
            }
        }
    }
}

// ---------------------------------------------------------------------------
// bn2 + relu: g_feat NHWC -> d_out features NCHW (fp32) AND writes the
// tf32-rounded CHANNEL-PERMUTED value back to g_feat (matcher input).
// grid (4, 256, BATCH), block 256.
// ---------------------------------------------------------------------------
__global__ void bn2t_kernel(float* __restrict__ out) {
    __shared__ float s_t[64][129];
    __shared__ float s_a[128], s_s[128];
    int tid = threadIdx.x;
    int x0 = blockIdx.x * 64, y = blockIdx.y, b = blockIdx.z;

    if (tid < 128) { s_a[tid] = g_stats2[tid]; s_s[tid] = g_stats2[128 + tid]; }
    __syncthreads();

    float* src = g_feat + ((size_t)(b * 256 + y) * 256 + x0) * 128;
#pragma unroll
    for (int i = 0; i < 32; ++i) {
        int idx = tid + i * 256;
        int px = idx >> 7, ch = idx & 127;
        float v = src[(size_t)px * 128 + ch];
        s_t[px][ch] = fmaxf(fmaf(s_a[ch], v, s_s[ch]), 0.f);
    }
    __syncthreads();
#pragma unroll
    for (int i = 0; i < 32; ++i) {
        int idx = tid + i * 256;
        int px = idx >> 7, ch = idx & 127;
        int k = ch & 31;
        int dst = (ch & ~31) + ((k & 3) * 8 + (k >> 2));
        src[(size_t)px * 128 + dst] = to_tf32(s_t[px][ch]);
    }
#pragma unroll
    for (int i = 0; i < 32; ++i) {
        int idx = tid + i * 256;
        int ch = idx >> 6, px = idx & 63;
        out[FEAT_OFF + ((size_t)(b * 128 + ch)) * HW + (size_t)y * 256 + x0 + px] = s_t[px][ch];
    }
}

// ---------------------------------------------------------------------------
// fused head: per-pixel 190->64 (relu) ->1 (sigmoid) and 190->4 + softmax/sig.
// ALL weights staged once in dynamic smem. 52 KB/CTA.
// ---------------------------------------------------------------------------
__global__ __launch_bounds__(256)
void head_kernel(const float* __restrict__ out_ro,
                 float* __restrict__ out,
                 const float* __restrict__ w1,
                 const float* __restrict__ b1,
                 const float* __restrict__ w2,
                 const float* __restrict__ b2,
                 const float* __restrict__ wc,
                 const float* __restrict__ bc) {
    extern __shared__ float hs[];            // [w1: 190*64][cls: 190*4][w2: 64][b1: 64]
    float* s_w1  = hs;
    float* s_cls = hs + QCIN * 64;
    float* s_w2  = hs + QCIN * 64 + QCIN * 4;
    float* s_b1  = s_w2 + 64;
    int tid = threadIdx.x;

    for (int i = tid; i < QCIN * 64; i += 256) {
        int c = i >> 6, o = i & 63;
        s_w1[i] = w1[o * QCIN + c];
    }
    for (int i = tid; i < QCIN * 4; i += 256) {
        int c = i >> 2, o = i & 3;
        s_cls[i] = wc[o * QCIN + c];
    }
    if (tid < 64) { s_w2[tid] = w2[tid]; s_b1[tid] = b1[tid]; }
    __syncthreads();

    int p = blockIdx.x * 256 + tid;
    int b = p >> 16, pix = p & 65535;

    const float* featp = out_ro + FEAT_OFF + ((size_t)(b * C2)) * HW + pix;
    const float* amp   = out_ro + AM_OFF + ((size_t)(b * NPAT)) * HW + pix;
    const float* anp   = out_ro + ANM_OFF + ((size_t)(b * NANOM)) * HW + pix;

    float acc[64];
#pragma unroll
    for (int o = 0; o < 64; ++o) acc[o] = 0.f;
    float cacc[4] = {0.f, 0.f, 0.f, 0.f};

#pragma unroll 4
    for (int c = 0; c < QCIN; ++c) {
        float v;
        if (c < C2)             v = featp[(size_t)c * HW];
        else if (c < C2 + NPAT) v = amp[(size_t)(c - C2) * HW];
        else                    v = anp[(size_t)(c - C2 - NPAT) * HW];
        const float* wp = &s_w1[c * 64];
#pragma unroll
        for (int o = 0; o < 64; ++o) acc[o] = fmaf(v, wp[o], acc[o]);
        const float* cp = &s_cls[c * 4];
        cacc[0] = fmaf(v, cp[0], cacc[0]);
        cacc[1] = fmaf(v, cp[1], cacc[1]);
        cacc[2] = fmaf(v, cp[2], cacc[2]);
        cacc[3] = fmaf(v, cp[3], cacc[3]);
    }

    float qs = 0.f;
#pragma unroll
    for (int o = 0; o < 64; ++o) {
        float q = fmaxf(acc[o] + s_b1[o], 0.f);
        qs = fmaf(q, s_w2[o], qs);
    }
    float quality = sigmoidf_(qs + b2[0]);

    float c0 = cacc[0] + bc[0];
    float c1 = cacc[1] + bc[1];
    float c2 = cacc[2] + bc[2];
    float c3 = cacc[3] + bc[3];
    float m = fmaxf(c0, fmaxf(c1, c2));
    float e0 = __expf(c0 - m), e1 = __expf(c1 - m), e2 = __expf(c2 - m);
    float inv = 1.f / (e0 + e1 + e2);

    size_t pb = (size_t)b * HW + pix;
    out[RL_OFF + ((size_t)(b * 3)) * HW + pix]     = c0;
    out[RL_OFF + ((size_t)(b * 3 + 1)) * HW + pix] = c1;
    out[RL_OFF + ((size_t)(b * 3 + 2)) * HW + pix] = c2;
    out[AL_OFF + pb] = c3;
    out[QS_OFF + pb] = quality;
    out[RP_OFF + ((size_t)(b * 3)) * HW + pix]     = e0 * inv;
    out[RP_OFF + ((size_t)(b * 3 + 1)) * HW + pix] = e1 * inv;
    out[RP_OFF + ((size_t)(b * 3 + 2)) * HW + pix] = e2 * inv;
    out[AP_OFF + pb] = sigmoidf_(c3);
}

// ---------------------------------------------------------------------------
extern "C" void kernel_launch(void* const* d_in, const int* in_sizes, int n_in,
                              void* d_out, int out_size) {
    (void)in_sizes; (void)n_in; (void)out_size;
    const float* x       = (const float*)d_in[0];
    const float* conv1_w = (const float*)d_in[1];
    const float* conv1_b = (const float*)d_in[2];
    const float* bn1_g   = (const float*)d_in[3];
    const float* bn1_b   = (const float*)d_in[4];
    const float* conv2_w = (const float*)d_in[5];
    const float* conv2_b = (const float*)d_in[6];
    const float* bn2_g   = (const float*)d_in[7];
    const float* bn2_b   = (const float*)d_in[8];
    const float* core_p  = (const float*)d_in[9];
    const float* clad_p  = (const float*)d_in[10];
    const float* ferr_p  = (const float*)d_in[11];
    const float* anom_p  = (const float*)d_in[12];
    const float* qa1_w   = (const float*)d_in[13];
    const float* qa1_b   = (const float*)d_in[14];
    const float* qa2_w   = (const float*)d_in[15];
    const float* qa2_b   = (const float*)d_in[16];
    const float* cls_w   = (const float*)d_in[17];
    const float* cls_b   = (const float*)d_in[18];
    float* out = (float*)d_out;

    const int smem_c2 = 3 * 136 * 36 * 4;           // 58752 (conv2 B triple-buffer)
    const int smem_mt = 2 * 264 * 36 * 4;           // 76032 (matcher B double-buffer)
    const int smem_hd = (QCIN * 64 + QCIN * 4 + 128) * 4;   // 52192
    cudaFuncSetAttribute(conv2_kernel,
                         cudaFuncAttributeMaxDynamicSharedMemorySize, smem_c2);
    cudaFuncSetAttribute(matcher_kernel,
                         cudaFuncAttributeMaxDynamicSharedMemorySize, smem_mt);
    cudaFuncSetAttribute(head_kernel,
                         cudaFuncAttributeMaxDynamicSharedMemorySize, smem_hd);

    float* d_stats1; cudaGetSymbolAddress((void**)&d_stats1, g_stats1);
    float* d_stats2; cudaGetSymbolAddress((void**)&d_stats2, g_stats2);
    float* d_h1n;    cudaGetSymbolAddress((void**)&d_h1n, g_h1n);
    float* d_feat;   cudaGetSymbolAddress((void**)&d_feat, g_feat);
    float* d_w2p;    cudaGetSymbolAddress((void**)&d_w2p, g_w2p);
    float* d_mwp;    cudaGetSymbolAddress((void**)&d_mwp, g_mwp);

    // [0] conv1 -> h1 NHWC raw + bn1 stats partials + permuted weight packing
    conv1_kernel<<<dim3(8, 16, 21), 256>>>(x, conv1_w, conv1_b,
                                           conv2_w, core_p, clad_p, ferr_p, anom_p);
    // [1] bn1 affine
    stats_p2v<C1, 512><<<C1, 256>>>(bn1_g, bn1_b, d_stats1);
    // [2] apply bn1+relu+tf32, channel-permuted, in place
    apply1_kernel<<<16384, 256>>>();
    // [3] conv2 shift-reuse tf32 gemm (3-stage) -> g_feat NHWC raw + bn2 partials
    conv2_kernel<<<dim3(2, 256, BATCH), 256, smem_c2>>>(
        d_h1n, d_w2p, conv2_b, d_feat);
    // [4] bn2 affine
    stats_p2v<C2, 2048><<<C2, 256>>>(bn2_g, bn2_b, d_stats2);
    // [5] bn2+relu: NCHW features to d_out + permuted tf32 back to g_feat
    bn2t_kernel<<<dim3(4, 256, BATCH), 256>>>(out);
    // [6] matcher shift-reuse tf32 gemm (NTILE=256) -> AM/ANM slabs
    matcher_kernel<<<dim3(256, BATCH), 256, smem_mt>>>(d_feat, d_mwp, out);
    // [7] fused 1x1 head (single-stage weights) -> remaining 6 output slabs
    head_kernel<<<(BATCH * HW) / 256, 256, smem_hd>>>(
        out, out, qa1_w, qa1_b, qa2_w, qa2_b, cls_w, cls_b);
}